// round 13
// baseline (speedup 1.0000x reference)
#include <cuda_runtime.h>
#include <cuda_bf16.h>
#include <cstdint>

#define C_DIM 256
#define DF_DIM 1024
#define NB 8
#define H0 128
#define W0 128
#define T0 (NB*H0*W0)      /* 131072 */
#define H1 32
#define W1 32
#define T1 (NB*H1*W1)      /* 8192 */
#define NHEADS 8
#define DH 32
#define WS 8
#define LWIN 64

// ==================================================================
// Scratch (device globals — allocation-free)
// ==================================================================
__device__ float g_bufA  [(size_t)T0*C_DIM];
__device__ float g_bufB  [(size_t)T0*C_DIM];
__device__ float g_bufL0 [(size_t)T0*C_DIM];
__device__ __nv_bfloat16 g_qkvh[(size_t)T0*768];
__device__ __nv_bfloat16 g_qkvl[(size_t)T0*768];
__device__ __nv_bfloat16 g_ash[(size_t)T0*DF_DIM];
__device__ __nv_bfloat16 g_asl[(size_t)T0*DF_DIM];
__device__ __nv_bfloat16 g_l0h[(size_t)T0*C_DIM];
__device__ __nv_bfloat16 g_l0l[(size_t)T0*C_DIM];
__device__ __nv_bfloat16 g_fh [(size_t)T0*DF_DIM];
__device__ __nv_bfloat16 g_fl [(size_t)T0*DF_DIM];
__device__ __nv_bfloat16 g_wth[1048576];
__device__ __nv_bfloat16 g_wtl[1048576];

// ==================================================================
// PTX helpers
// ==================================================================
__device__ __forceinline__ uint32_t smem_u32(const void* p) {
    uint32_t a;
    asm("{ .reg .u64 t; cvta.to.shared.u64 t, %1; cvt.u32.u64 %0, t; }"
        : "=r"(a) : "l"(p));
    return a;
}

#define CP_ASYNC16(dst, src) \
    asm volatile("cp.async.cg.shared.global [%0], [%1], 16;" :: "r"(dst), "l"(src) : "memory")
#define CP_COMMIT() asm volatile("cp.async.commit_group;" ::: "memory")

__device__ __forceinline__ void ldm_x4(uint32_t* r, uint32_t addr) {
    asm volatile("ldmatrix.sync.aligned.m8n8.x4.shared.b16 {%0,%1,%2,%3}, [%4];"
        : "=r"(r[0]), "=r"(r[1]), "=r"(r[2]), "=r"(r[3]) : "r"(addr));
}
__device__ __forceinline__ void ldm_x2(uint32_t* r, uint32_t addr) {
    asm volatile("ldmatrix.sync.aligned.m8n8.x2.shared.b16 {%0,%1}, [%2];"
        : "=r"(r[0]), "=r"(r[1]) : "r"(addr));
}
__device__ __forceinline__ void ldm_x2_trans(uint32_t* r, uint32_t addr) {
    asm volatile("ldmatrix.sync.aligned.m8n8.x2.trans.shared.b16 {%0,%1}, [%2];"
        : "=r"(r[0]), "=r"(r[1]) : "r"(addr));
}
__device__ __forceinline__ void mma16816(float* c, const uint32_t* a, const uint32_t* b) {
    asm volatile("mma.sync.aligned.m16n8k16.row.col.f32.bf16.bf16.f32 "
        "{%0,%1,%2,%3}, {%4,%5,%6,%7}, {%8,%9}, {%0,%1,%2,%3};"
        : "+f"(c[0]), "+f"(c[1]), "+f"(c[2]), "+f"(c[3])
        : "r"(a[0]), "r"(a[1]), "r"(a[2]), "r"(a[3]), "r"(b[0]), "r"(b[1]));
}

__device__ __forceinline__ void split2(float v, __nv_bfloat16& h, __nv_bfloat16& l) {
    h = __float2bfloat16(v);
    l = __float2bfloat16(v - __bfloat162float(h));
}
__device__ __forceinline__ uint32_t bpack(__nv_bfloat16 a, __nv_bfloat16 b) {
    __nv_bfloat162 t(a, b);
    return *reinterpret_cast<uint32_t*>(&t);
}

// ==================================================================
// Transpose per-batch [P][Q] -> [Q][P], optional fused bf16 split
// ==================================================================
__global__ void transpose_split_kernel(const float* __restrict__ in,
                                       float* __restrict__ out,
                                       __nv_bfloat16* __restrict__ hi,
                                       __nv_bfloat16* __restrict__ lo,
                                       int P, int Q)
{
    __shared__ float tile[32][33];
    const size_t bofs = (size_t)blockIdx.z * P * Q;
    in += bofs;
    int p0 = blockIdx.y * 32;
    int q0 = blockIdx.x * 32;
    int tx = threadIdx.x, ty = threadIdx.y;
    #pragma unroll
    for (int i = ty; i < 32; i += 8)
        tile[i][tx] = in[(size_t)(p0 + i) * Q + q0 + tx];
    __syncthreads();
    #pragma unroll
    for (int i = ty; i < 32; i += 8) {
        float v = tile[tx][i];
        size_t o = bofs + (size_t)(q0 + i) * P + p0 + tx;
        out[o] = v;
        if (hi) {
            __nv_bfloat16 h, l;
            split2(v, h, l);
            hi[o] = h;
            lo[o] = l;
        }
    }
}

// ==================================================================
// Batched weight prep: 10 matrices, transpose+split in ONE launch.
// ==================================================================
struct WPrepArgs {
    const float* src[10];
    int K[10];
    int N[10];
    int off[10];
};

__global__ void wprep_kernel(WPrepArgs a,
                             __nv_bfloat16* __restrict__ hi_base,
                             __nv_bfloat16* __restrict__ lo_base)
{
    __shared__ float tile[32][33];
    const int j = blockIdx.z;
    const int K = a.K[j], N = a.N[j];
    const int n0 = blockIdx.x * 32;
    const int k0 = blockIdx.y * 32;
    if (n0 >= N || k0 >= K) return;
    const float* W = a.src[j];
    __nv_bfloat16* hi = hi_base + a.off[j];
    __nv_bfloat16* lo = lo_base + a.off[j];
    int tx = threadIdx.x, ty = threadIdx.y;
    #pragma unroll
    for (int i = ty; i < 32; i += 8)
        tile[i][tx] = W[(size_t)(k0 + i) * N + n0 + tx];
    __syncthreads();
    #pragma unroll
    for (int i = ty; i < 32; i += 8) {
        float v = tile[tx][i];
        __nv_bfloat16 h, l;
        split2(v, h, l);
        size_t o = (size_t)(n0 + i) * K + k0 + tx;
        hi[o] = h;
        lo[o] = l;
    }
}

// ==================================================================
// mma.sync bf16x3 GEMM (unchanged)
// ==================================================================
#define BM 128
#define BN 256
#define BK 32
#define LDS 40
#define A_MAT (128*LDS*2)
#define B_MAT (256*LDS*2)
#define STG_BYTES (2*A_MAT + 2*B_MAT)
#define STAGES 3
#define GEMM_SMEM (STAGES*STG_BYTES)

__device__ __forceinline__ void load_tiles(uint32_t st,
    const __nv_bfloat16* ah, const __nv_bfloat16* al,
    const __nv_bfloat16* bh, const __nv_bfloat16* bl,
    int K, int k0, int tid)
{
    {
        int row = tid >> 1;
        int cb  = (tid & 1) * 32;
        uint32_t doff = (uint32_t)row * (LDS*2) + cb;
        const char* pa = (const char*)(ah + (size_t)row * K + k0) + cb;
        const char* pl = (const char*)(al + (size_t)row * K + k0) + cb;
        CP_ASYNC16(st + doff,              pa);
        CP_ASYNC16(st + doff + 16,         pa + 16);
        CP_ASYNC16(st + A_MAT + doff,      pl);
        CP_ASYNC16(st + A_MAT + doff + 16, pl + 16);
    }
    {
        int row = tid;
        uint32_t doff = (uint32_t)row * (LDS*2);
        const char* pb = (const char*)(bh + (size_t)row * K + k0);
        const char* pc = (const char*)(bl + (size_t)row * K + k0);
        uint32_t b0 = st + 2*A_MAT + doff;
        uint32_t b1 = st + 2*A_MAT + B_MAT + doff;
        #pragma unroll
        for (int c = 0; c < 4; c++) {
            CP_ASYNC16(b0 + c*16, pb + c*16);
            CP_ASYNC16(b1 + c*16, pc + c*16);
        }
    }
}

__global__ __launch_bounds__(256, 1)
void gemm_tc_kernel(int M, int N, int K,
    const __nv_bfloat16* __restrict__ Ah, const __nv_bfloat16* __restrict__ Al,
    const __nv_bfloat16* __restrict__ Bh, const __nv_bfloat16* __restrict__ Bl,
    const float* __restrict__ bias, const float* __restrict__ Rm,
    const float* __restrict__ lnG, const float* __restrict__ lnB,
    float* __restrict__ Cf,
    __nv_bfloat16* __restrict__ Ch, __nv_bfloat16* __restrict__ Cl,
    int relu)
{
    extern __shared__ char smem[];
    const uint32_t sbase = smem_u32(smem);
    const int tid  = threadIdx.x;
    const int wid  = tid >> 5;
    const int lane = tid & 31;
    const int wm = wid >> 2;
    const int wn = wid & 3;

    const int n0 = blockIdx.x * BN;
    const int m0 = blockIdx.y * BM;
    const __nv_bfloat16* ah = Ah + (size_t)m0 * K;
    const __nv_bfloat16* al = Al + (size_t)m0 * K;
    const __nv_bfloat16* bh = Bh + (size_t)n0 * K;
    const __nv_bfloat16* bl = Bl + (size_t)n0 * K;

    const int NC = K / BK;

    float acc[4][8][4];
    #pragma unroll
    for (int mt = 0; mt < 4; mt++)
        #pragma unroll
        for (int nt = 0; nt < 8; nt++)
            #pragma unroll
            for (int j = 0; j < 4; j++) acc[mt][nt][j] = 0.f;

    #pragma unroll
    for (int s = 0; s < STAGES - 1; s++) {
        if (s < NC) load_tiles(sbase + s * STG_BYTES, ah, al, bh, bl, K, s * BK, tid);
        CP_COMMIT();
    }

    const int lr16 = lane & 15;
    const int lc16 = lane >> 4;
    const int lr8  = lr16 & 7;
    const int lc8  = lr16 >> 3;

    for (int i = 0; i < NC; i++) {
        asm volatile("cp.async.wait_group %0;" :: "n"(STAGES - 2));
        __syncthreads();

        int is = i + STAGES - 1;
        if (is < NC) load_tiles(sbase + (is % STAGES) * STG_BYTES,
                                ah, al, bh, bl, K, is * BK, tid);
        CP_COMMIT();

        const uint32_t st  = sbase + (i % STAGES) * STG_BYTES;
        const uint32_t sAh = st;
        const uint32_t sAl = st + A_MAT;
        const uint32_t sBh = st + 2*A_MAT;
        const uint32_t sBl = st + 2*A_MAT + B_MAT;

        #pragma unroll
        for (int ks = 0; ks < 2; ks++) {
            uint32_t ahf[4][4], alf[4][4];
            #pragma unroll
            for (int mt = 0; mt < 4; mt++) {
                uint32_t off = ((uint32_t)(wm*64 + mt*16 + lr16) * LDS
                                + ks*16 + lc16*8) * 2;
                ldm_x4(ahf[mt], sAh + off);
                ldm_x4(alf[mt], sAl + off);
            }
            #pragma unroll
            for (int nh = 0; nh < 2; nh++) {
                uint32_t bhf[4][2], blf[4][2];
                #pragma unroll
                for (int nt = 0; nt < 4; nt++) {
                    uint32_t off = ((uint32_t)(wn*64 + nh*32 + nt*8 + lr8) * LDS
                                    + ks*16 + lc8*8) * 2;
                    ldm_x2(bhf[nt], sBh + off);
                    ldm_x2(blf[nt], sBl + off);
                }
                #pragma unroll
                for (int mt = 0; mt < 4; mt++)
                    #pragma unroll
                    for (int nt = 0; nt < 4; nt++) {
                        float* c = acc[mt][nh*4 + nt];
                        mma16816(c, ahf[mt], bhf[nt]);
                        mma16816(c, ahf[mt], blf[nt]);
                        mma16816(c, alf[mt], bhf[nt]);
                    }
            }
        }
    }

    // ---------------- Epilogue ----------------
    const int rit = lane >> 2;
    const int cit = (lane & 3) * 2;

    #pragma unroll
    for (int mt = 0; mt < 4; mt++) {
        #pragma unroll
        for (int nt = 0; nt < 8; nt++) {
            int gc = n0 + wn*64 + nt*8 + cit;
            float* c = acc[mt][nt];
            if (bias) {
                float2 bb = *(const float2*)(bias + gc);
                c[0] += bb.x; c[1] += bb.y; c[2] += bb.x; c[3] += bb.y;
            }
            if (Rm) {
                int gr0 = m0 + wm*64 + mt*16 + rit;
                float2 r0 = *(const float2*)(Rm + (size_t)gr0 * N + gc);
                float2 r1 = *(const float2*)(Rm + (size_t)(gr0 + 8) * N + gc);
                c[0] += r0.x; c[1] += r0.y; c[2] += r1.x; c[3] += r1.y;
            }
            if (relu) {
                c[0] = fmaxf(c[0], 0.f); c[1] = fmaxf(c[1], 0.f);
                c[2] = fmaxf(c[2], 0.f); c[3] = fmaxf(c[3], 0.f);
            }
        }
    }

    if (lnG) {
        float2* red = (float2*)smem;
        __syncthreads();
        #pragma unroll
        for (int mt = 0; mt < 4; mt++) {
            float s0 = 0.f, q0 = 0.f, s1 = 0.f, q1 = 0.f;
            #pragma unroll
            for (int nt = 0; nt < 8; nt++) {
                float* c = acc[mt][nt];
                s0 += c[0] + c[1]; q0 += c[0]*c[0] + c[1]*c[1];
                s1 += c[2] + c[3]; q1 += c[2]*c[2] + c[3]*c[3];
            }
            #pragma unroll
            for (int o = 1; o < 4; o <<= 1) {
                s0 += __shfl_xor_sync(0xffffffffu, s0, o);
                q0 += __shfl_xor_sync(0xffffffffu, q0, o);
                s1 += __shfl_xor_sync(0xffffffffu, s1, o);
                q1 += __shfl_xor_sync(0xffffffffu, q1, o);
            }
            if ((lane & 3) == 0) {
                int r0 = wm*64 + mt*16 + rit;
                red[r0*4 + wn]       = make_float2(s0, q0);
                red[(r0 + 8)*4 + wn] = make_float2(s1, q1);
            }
        }
        __syncthreads();
        #pragma unroll
        for (int mt = 0; mt < 4; mt++) {
            int r0 = wm*64 + mt*16 + rit;
            float S0 = 0.f, Q0 = 0.f, S1 = 0.f, Q1 = 0.f;
            #pragma unroll
            for (int w = 0; w < 4; w++) {
                float2 p0 = red[r0*4 + w];
                float2 p1 = red[(r0 + 8)*4 + w];
                S0 += p0.x; Q0 += p0.y;
                S1 += p1.x; Q1 += p1.y;
            }
            float mu0 = S0 * (1.0f/256.0f);
            float mu1 = S1 * (1.0f/256.0f);
            float rs0 = rsqrtf(Q0 * (1.0f/256.0f) - mu0*mu0 + 1e-5f);
            float rs1 = rsqrtf(Q1 * (1.0f/256.0f) - mu1*mu1 + 1e-5f);
            #pragma unroll
            for (int nt = 0; nt < 8; nt++) {
                int gc = wn*64 + nt*8 + cit;
                float2 g2 = *(const float2*)(lnG + gc);
                float2 b2 = *(const float2*)(lnB + gc);
                float* c = acc[mt][nt];
                c[0] = (c[0] - mu0) * rs0 * g2.x + b2.x;
                c[1] = (c[1] - mu0) * rs0 * g2.y + b2.y;
                c[2] = (c[2] - mu1) * rs1 * g2.x + b2.x;
                c[3] = (c[3] - mu1) * rs1 * g2.y + b2.y;
            }
        }
    }

    #pragma unroll
    for (int mt = 0; mt < 4; mt++) {
        #pragma unroll
        for (int nt = 0; nt < 8; nt++) {
            int gr0 = m0 + wm*64 + mt*16 + rit;
            int gc  = n0 + wn*64 + nt*8 + cit;
            size_t o0 = (size_t)gr0 * N + gc;
            size_t o1 = (size_t)(gr0 + 8) * N + gc;
            float* c = acc[mt][nt];
            if (Cf) {
                *(float2*)(Cf + o0) = make_float2(c[0], c[1]);
                *(float2*)(Cf + o1) = make_float2(c[2], c[3]);
            }
            if (Ch) {
                __nv_bfloat16 h0, h1, h2, h3, l0, l1, l2, l3;
                split2(c[0], h0, l0); split2(c[1], h1, l1);
                split2(c[2], h2, l2); split2(c[3], h3, l3);
                *(__nv_bfloat162*)(Ch + o0) = __nv_bfloat162(h0, h1);
                *(__nv_bfloat162*)(Ch + o1) = __nv_bfloat162(h2, h3);
                *(__nv_bfloat162*)(Cl + o0) = __nv_bfloat162(l0, l1);
                *(__nv_bfloat162*)(Cl + o1) = __nv_bfloat162(l2, l3);
            }
        }
    }
}

// ==================================================================
// Windowed attention — tensor-core FA2-style, 4 HEADS PER BLOCK.
// Block = (window, head-group of 4), 512 threads (16 warps; 4/head).
// Loads are 256B contiguous per row per matrix -> full 128B-line
// utilization (fixes the 2.3x DRAM amplification seen in ncu).
// Row stride 272B keeps ldmatrix bank-conflict-free (8 rows step
// 4 banks each -> all 32 banks covered).
// ==================================================================
#define HG 4                     /* heads per block */
#define ALD4 136                 /* smem row, elements (128 + 8 pad) */
#define SM_MAT (LWIN*ALD4)       /* elements per matrix */
#define ATTN_SMEM (6*SM_MAT*2)   /* bytes = 104448 */

__global__ __launch_bounds__(512)
void win_attn_kernel(const __nv_bfloat16* __restrict__ Qhp,
                     const __nv_bfloat16* __restrict__ Qlp, int qs,
                     const __nv_bfloat16* __restrict__ Khp,
                     const __nv_bfloat16* __restrict__ Klp,
                     const __nv_bfloat16* __restrict__ Vhp,
                     const __nv_bfloat16* __restrict__ Vlp, int kvs,
                     __nv_bfloat16* __restrict__ Oh, __nv_bfloat16* __restrict__ Ol,
                     int qH, int qW, int kH, int kW, int ks)
{
    extern __shared__ __nv_bfloat16 sm[];
    __nv_bfloat16 *SQh = sm,            *SQl = sm + SM_MAT,
                  *SKh = sm + 2*SM_MAT, *SKl = sm + 3*SM_MAT,
                  *SVh = sm + 4*SM_MAT, *SVl = sm + 5*SM_MAT;

    const int tid  = threadIdx.x;
    const int grp  = blockIdx.y;          // head group (0..1)
    const int win  = blockIdx.x;
    const int nWw  = qW / WS;
    const int wpb  = (qH / WS) * nWw;
    const int n    = win / wpb;
    const int r    = win % wpb;
    const int wh   = r / nWw, ww = r % nWw;

    const size_t qbase = (size_t)n * qH * qW;
    const size_t kbase = (size_t)n * kH * kW;
    const int co = grp * (HG * DH);       // slice base in Q/K/V rows

    // ---- load: 64 rows x 128 elems per matrix; 16 chunks/row ----
    #pragma unroll
    for (int it = 0; it < 2; it++) {
        int idx = tid + it * 512;
        int row = idx >> 4;
        int c8  = (idx & 15) * 8;         // element offset in 128-wide slice
        int i = row >> 3, j = row & 7;
        size_t qt = qbase + (size_t)(wh * WS + i) * qW + (ww * WS + j);
        int ki = (wh * ks + i) % kH;
        int kj = (ww * ks + j) % kW;
        size_t kt = kbase + (size_t)ki * kW + kj;

        *(uint4*)&SQh[row*ALD4 + c8] = *(const uint4*)(Qhp + qt * qs + co + c8);
        *(uint4*)&SQl[row*ALD4 + c8] = *(const uint4*)(Qlp + qt * qs + co + c8);
        *(uint4*)&SKh[row*ALD4 + c8] = *(const uint4*)(Khp + kt * kvs + co + c8);
        *(uint4*)&SKl[row*ALD4 + c8] = *(const uint4*)(Klp + kt * kvs + co + c8);
        *(uint4*)&SVh[row*ALD4 + c8] = *(const uint4*)(Vhp + kt * kvs + co + c8);
        *(uint4*)&SVl[row*ALD4 + c8] = *(const uint4*)(Vlp + kt * kvs + co + c8);
    }
    __syncthreads();

    const int wid  = tid >> 5;
    const int lane = tid & 31;
    const int hg   = wid >> 2;            // head within group (0..3)
    const int w4   = wid & 3;             // warp within head
    const int hb   = hg * DH;             // column base within smem row
    const int lr16 = lane & 15;
    const int lc16 = lane >> 4;
    const int lr8  = lr16 & 7;
    const int lc8  = lr16 >> 3;

    const uint32_t aQh = smem_u32(SQh), aQl = smem_u32(SQl);
    const uint32_t aKh = smem_u32(SKh), aKl = smem_u32(SKl);
    const uint32_t aVh = smem_u32(SVh), aVl = smem_u32(SVl);

    // ---- S = Q @ K^T (bf16x3, fp32 accum) ----
    float sacc[8][4];
    #pragma unroll
    for (int nt = 0; nt < 8; nt++)
        #pragma unroll
        for (int j = 0; j < 4; j++) sacc[nt][j] = 0.f;

    #pragma unroll
    for (int k2 = 0; k2 < 2; k2++) {
        uint32_t qh[4], ql[4];
        uint32_t offA = ((uint32_t)(w4*16 + lr16) * ALD4 + hb + k2*16 + lc16*8) * 2;
        ldm_x4(qh, aQh + offA);
        ldm_x4(ql, aQl + offA);
        #pragma unroll
        for (int nt = 0; nt < 8; nt++) {
            uint32_t kh[2], kl[2];
            uint32_t offB = ((uint32_t)(nt*8 + lr8) * ALD4 + hb + k2*16 + lc8*8) * 2;
            ldm_x2(kh, aKh + offB);
            ldm_x2(kl, aKl + offB);
            mma16816(sacc[nt], qh, kh);
            mma16816(sacc[nt], qh, kl);
            mma16816(sacc[nt], ql, kh);
        }
    }

    // ---- exp (max-free) + row sums ----
    const float SC = 0.17677669529663687f;
    float s0 = 0.f, s1 = 0.f;
    #pragma unroll
    for (int nt = 0; nt < 8; nt++) {
        sacc[nt][0] = __expf(sacc[nt][0] * SC);
        sacc[nt][1] = __expf(sacc[nt][1] * SC);
        sacc[nt][2] = __expf(sacc[nt][2] * SC);
        sacc[nt][3] = __expf(sacc[nt][3] * SC);
        s0 += sacc[nt][0] + sacc[nt][1];
        s1 += sacc[nt][2] + sacc[nt][3];
    }
    s0 += __shfl_xor_sync(0xffffffffu, s0, 1);
    s0 += __shfl_xor_sync(0xffffffffu, s0, 2);
    s1 += __shfl_xor_sync(0xffffffffu, s1, 1);
    s1 += __shfl_xor_sync(0xffffffffu, s1, 2);
    const float inv0 = 1.0f / s0;
    const float inv1 = 1.0f / s1;

    // ---- O = P @ V (bf16x3; P accum->A-fragment identity) ----
    float oacc[4][4];
    #pragma unroll
    for (int nt = 0; nt < 4; nt++)
        #pragma unroll
        for (int j = 0; j < 4; j++) oacc[nt][j] = 0.f;

    #pragma unroll
    for (int kk = 0; kk < 4; kk++) {
        uint32_t ph[4], pl[4];
        #pragma unroll
        for (int h2 = 0; h2 < 2; h2++) {
            float* sp = sacc[kk*2 + h2];
            #pragma unroll
            for (int g = 0; g < 2; g++) {
                float p0 = sp[g*2], p1 = sp[g*2 + 1];
                __nv_bfloat16 hh0 = __float2bfloat16(p0);
                __nv_bfloat16 hh1 = __float2bfloat16(p1);
                ph[h2*2 + g] = bpack(hh0, hh1);
                pl[h2*2 + g] = bpack(
                    __float2bfloat16(p0 - __bfloat162float(hh0)),
                    __float2bfloat16(p1 - __bfloat162float(hh1)));
            }
        }
        #pragma unroll
        for (int nt = 0; nt < 4; nt++) {
            uint32_t vh[2], vl[2];
            uint32_t offV = ((uint32_t)(kk*16 + lr16) * ALD4 + hb + nt*8) * 2;
            ldm_x2_trans(vh, aVh + offV);
            ldm_x2_trans(vl, aVl + offV);
            mma16816(oacc[nt], ph, vh);
            mma16816(oacc[nt], ph, vl);
            mma16816(oacc[nt], pl, vh);
        }
    }

    // ---- normalize + store bf16 hi/lo (stride C_DIM) ----
    const int cit = (lane & 3) * 2;
    const int oc  = co + hb;              // output column base (C_DIM layout)
    int r0 = w4*16 + (lane >> 2);
    int r1 = r0 + 8;
    int i0 = r0 >> 3, j0 = r0 & 7;
    int i1 = r1 >> 3, j1 = r1 & 7;
    size_t t0 = qbase + (size_t)(wh * WS + i0) * qW + (ww * WS + j0);
    size_t t1 = qbase + (size_t)(wh * WS + i1) * qW + (ww * WS + j1);
    size_t ob0 = t0 * C_DIM + oc + cit;
    size_t ob1 = t1 * C_DIM + oc + cit;

    #pragma unroll
    for (int nt = 0; nt < 4; nt++) {
        float v0 = oacc[nt][0] * inv0;
        float v1 = oacc[nt][1] * inv0;
        float v2 = oacc[nt][2] * inv1;
        float v3 = oacc[nt][3] * inv1;
        __nv_bfloat16 h0, h1, h2, h3, l0, l1, l2, l3;
        split2(v0, h0, l0); split2(v1, h1, l1);
        split2(v2, h2, l2); split2(v3, h3, l3);
        *(__nv_bfloat162*)(Oh + ob0 + nt*8) = __nv_bfloat162(h0, h1);
        *(__nv_bfloat162*)(Ol + ob0 + nt*8) = __nv_bfloat162(l0, l1);
        *(__nv_bfloat162*)(Oh + ob1 + nt*8) = __nv_bfloat162(h2, h3);
        *(__nv_bfloat162*)(Ol + ob1 + nt*8) = __nv_bfloat162(l2, l3);
    }
}

// ==================================================================
// 4x4 average pool (NHWC), fp32 + bf16 hi/lo out
// ==================================================================
__global__ __launch_bounds__(256)
void avgpool_kernel(const float* __restrict__ in, float* __restrict__ outf,
                    __nv_bfloat16* __restrict__ outh, __nv_bfloat16* __restrict__ outl)
{
    int t = blockIdx.x;
    int c = threadIdx.x;
    int n = t / (H1 * W1);
    int r = t % (H1 * W1);
    int oh = r / W1, ow = r % W1;
    float s = 0.f;
    #pragma unroll
    for (int dy = 0; dy < 4; dy++)
        #pragma unroll
        for (int dx = 0; dx < 4; dx++) {
            size_t tok = (size_t)n * H0 * W0 + (size_t)(oh * 4 + dy) * W0 + (ow * 4 + dx);
            s += in[tok * C_DIM + c];
        }
    s *= (1.0f / 16.0f);
    size_t o = (size_t)t * C_DIM + c;
    outf[o] = s;
    __nv_bfloat16 h, l;
    split2(s, h, l);
    outh[o] = h;
    outl[o] = l;
}

// ==================================================================
// Host side
// ==================================================================
#define WT_QKV  0
#define WT_SAF  196608
#define WT_CAQ  262144
#define WT_CAKV 327680
#define WT_CAF  458752
#define WT_W1   524288
#define WT_W2   786432

extern "C" void kernel_launch(void* const* d_in, const int* in_sizes, int n_in,
                              void* d_out, int out_size)
{
    const float* x       = (const float*)d_in[0];
    const float* sa_wq   = (const float*)d_in[1];
    const float* sa_wk   = (const float*)d_in[2];
    const float* sa_wv   = (const float*)d_in[3];
    const float* sa_wf   = (const float*)d_in[4];
    const float* sa_bf   = (const float*)d_in[5];
    const float* ca_wq   = (const float*)d_in[6];
    const float* ca_wk   = (const float*)d_in[7];
    const float* ca_wv   = (const float*)d_in[8];
    const float* ca_wf   = (const float*)d_in[9];
    const float* ca_bf   = (const float*)d_in[10];
    const float* ln_self_g = (const float*)d_in[11];
    const float* ln_self_b = (const float*)d_in[12];
    const float* ln_cross_g= (const float*)d_in[13];
    const float* ln_cross_b= (const float*)d_in[14];
    const float* ffn_w1  = (const float*)d_in[15];
    const float* ffn_b1  = (const float*)d_in[16];
    const float* ffn_w2  = (const float*)d_in[17];
    const float* ffn_b2  = (const float*)d_in[18];
    const float* ln_out_g= (const float*)d_in[19];
    const float* ln_out_b= (const float*)d_in[20];
    float* out = (float*)d_out;

    float *bufA, *bufB, *bufL0;
    __nv_bfloat16 *qkvh, *qkvl, *ash, *asl, *l0h, *l0l, *fh, *fl, *wth, *wtl;
    cudaGetSymbolAddress((void**)&bufA,  g_bufA);
    cudaGetSymbolAddress((void**)&bufB,  g_bufB);
    cudaGetSymbolAddress((void**)&bufL0, g_bufL0);
    cudaGetSymbolAddress((void**)&qkvh,  g_qkvh);
    cudaGetSymbolAddress((void**)&qkvl,  g_qkvl);
    cudaGetSymbolAddress((void**)&ash,   g_ash);
    cudaGetSymbolAddress((void**)&asl,   g_asl);
    cudaGetSymbolAddress((void**)&l0h,   g_l0h);
    cudaGetSymbolAddress((void**)&l0l,   g_l0l);
    cudaGetSymbolAddress((void**)&fh,    g_fh);
    cudaGetSymbolAddress((void**)&fl,    g_fl);
    cudaGetSymbolAddress((void**)&wth,   g_wth);
    cudaGetSymbolAddress((void**)&wtl,   g_wtl);

    cudaFuncSetAttribute(gemm_tc_kernel,
                         cudaFuncAttributeMaxDynamicSharedMemorySize, GEMM_SMEM);
    cudaFuncSetAttribute(win_attn_kernel,
                         cudaFuncAttributeMaxDynamicSharedMemorySize, ATTN_SMEM);

    dim3 tb(32, 8);

    auto gemm = [&](int M, int N, int K,
                    const __nv_bfloat16* Ahp, const __nv_bfloat16* Alp,
                    const __nv_bfloat16* Bhp, const __nv_bfloat16* Blp,
                    const float* bias, const float* resid,
                    const float* lnG, const float* lnB,
                    float* Cf, __nv_bfloat16* Ch, __nv_bfloat16* Cl, int relu) {
        dim3 grid(N / BN, M / BM);
        gemm_tc_kernel<<<grid, 256, GEMM_SMEM>>>(M, N, K, Ahp, Alp, Bhp, Blp,
                                                 bias, resid, lnG, lnB,
                                                 Cf, Ch, Cl, relu);
    };

    // --- batched weight prep (one launch) ---
    {
        WPrepArgs a;
        const float* srcs[10] = {sa_wq, sa_wk, sa_wv, sa_wf, ca_wq,
                                 ca_wk, ca_wv, ca_wf, ffn_w1, ffn_w2};
        int Ks[10]  = {256,256,256,256,256,256,256,256,256,1024};
        int Ns[10]  = {256,256,256,256,256,256,256,256,1024,256};
        int offs[10] = {WT_QKV, WT_QKV + 65536, WT_QKV + 131072, WT_SAF,
                        WT_CAQ, WT_CAKV, WT_CAKV + 65536, WT_CAF,
                        WT_W1, WT_W2};
        for (int j = 0; j < 10; j++) {
            a.src[j] = srcs[j]; a.K[j] = Ks[j]; a.N[j] = Ns[j]; a.off[j] = offs[j];
        }
        wprep_kernel<<<dim3(32, 32, 10), tb>>>(a, wth, wtl);
    }

    // 0. NCHW -> NHWC (+split)
    transpose_split_kernel<<<dim3(H0*W0/32, C_DIM/32, NB), tb>>>(x, bufA, ash, asl,
                                                                 C_DIM, H0*W0);

    // 1. Self-attention level 0
    gemm(T0, 768, 256, ash, asl, wth + WT_QKV, wtl + WT_QKV,
         nullptr, nullptr, nullptr, nullptr, nullptr, qkvh, qkvl, 0);
    win_attn_kernel<<<dim3(NB*16*16, NHEADS/HG), 512, ATTN_SMEM>>>(
        qkvh, qkvl, 768, qkvh + 256, qkvl + 256, qkvh + 512, qkvl + 512, 768,
        ash, asl, H0, W0, H0, W0, WS);
    gemm(T0, 256, 256, ash, asl, wth + WT_SAF, wtl + WT_SAF,
         sa_bf, bufA, ln_self_g, ln_self_b, bufL0, l0h, l0l, 0);

    // 2. avgpool
    avgpool_kernel<<<T1, 256>>>(bufL0, bufB, ash, asl);

    // 3. Self-attention level 1
    gemm(T1, 768, 256, ash, asl, wth + WT_QKV, wtl + WT_QKV,
         nullptr, nullptr, nullptr, nullptr, nullptr, qkvh, qkvl, 0);
    win_attn_kernel<<<dim3(NB*4*4, NHEADS/HG), 512, ATTN_SMEM>>>(
        qkvh, qkvl, 768, qkvh + 256, qkvl + 256, qkvh + 512, qkvl + 512, 768,
        ash, asl, H1, W1, H1, W1, WS);
    gemm(T1, 256, 256, ash, asl, wth + WT_SAF, wtl + WT_SAF,
         sa_bf, bufB, ln_self_g, ln_self_b, nullptr, ash, asl, 0);

    // 4. Cross-attention
    gemm(T1, 512, 256, ash, asl, wth + WT_CAKV, wtl + WT_CAKV,
         nullptr, nullptr, nullptr, nullptr, nullptr, qkvh, qkvl, 0);
    gemm(T0, 256, 256, l0h, l0l, wth + WT_CAQ, wtl + WT_CAQ,
         nullptr, nullptr, nullptr, nullptr, nullptr, fh, fl, 0);
    win_attn_kernel<<<dim3(NB*16*16, NHEADS/HG), 512, ATTN_SMEM>>>(
        fh, fl, 256, qkvh, qkvl, qkvh + 256, qkvl + 256, 512,
        ash, asl, H0, W0, H1, W1, 2);
    gemm(T0, 256, 256, ash, asl, wth + WT_CAF, wtl + WT_CAF,
         ca_bf, bufL0, ln_cross_g, ln_cross_b, bufB, ash, asl, 0);

    // 5. FFN (+fused final LN on FFN2)
    gemm(T0, 1024, 256, ash, asl, wth + WT_W1, wtl + WT_W1,
         ffn_b1, nullptr, nullptr, nullptr, nullptr, fh, fl, 1);
    gemm(T0, 256, 1024, fh, fl, wth + WT_W2, wtl + WT_W2,
         ffn_b2, bufB, ln_out_g, ln_out_b, bufL0, nullptr, nullptr, 0);

    // 6. NHWC -> NCHW
    transpose_split_kernel<<<dim3(C_DIM/32, H0*W0/32, NB), tb>>>(bufL0, out,
        nullptr, nullptr, H0*W0, C_DIM);
}

// round 14
// speedup vs baseline: 1.0238x; 1.0238x over previous
#include <cuda_runtime.h>
#include <cuda_bf16.h>
#include <cstdint>

#define C_DIM 256
#define DF_DIM 1024
#define NB 8
#define H0 128
#define W0 128
#define T0 (NB*H0*W0)      /* 131072 */
#define H1 32
#define W1 32
#define T1 (NB*H1*W1)      /* 8192 */
#define NHEADS 8
#define DH 32
#define WS 8
#define LWIN 64

// ==================================================================
// Scratch (device globals — allocation-free)
// ==================================================================
__device__ float g_bufA  [(size_t)T0*C_DIM];
__device__ float g_bufB  [(size_t)T0*C_DIM];
__device__ float g_bufL0 [(size_t)T0*C_DIM];
__device__ __nv_bfloat16 g_qkvh[(size_t)T0*768];
__device__ __nv_bfloat16 g_qkvl[(size_t)T0*768];
__device__ __nv_bfloat16 g_ash[(size_t)T0*DF_DIM];
__device__ __nv_bfloat16 g_asl[(size_t)T0*DF_DIM];
__device__ __nv_bfloat16 g_l0h[(size_t)T0*C_DIM];
__device__ __nv_bfloat16 g_l0l[(size_t)T0*C_DIM];
__device__ __nv_bfloat16 g_fh [(size_t)T0*DF_DIM];
__device__ __nv_bfloat16 g_fl [(size_t)T0*DF_DIM];
__device__ __nv_bfloat16 g_wth[1048576];
__device__ __nv_bfloat16 g_wtl[1048576];

// ==================================================================
// PTX helpers
// ==================================================================
__device__ __forceinline__ uint32_t smem_u32(const void* p) {
    uint32_t a;
    asm("{ .reg .u64 t; cvta.to.shared.u64 t, %1; cvt.u32.u64 %0, t; }"
        : "=r"(a) : "l"(p));
    return a;
}

#define CP_ASYNC16(dst, src) \
    asm volatile("cp.async.cg.shared.global [%0], [%1], 16;" :: "r"(dst), "l"(src) : "memory")
#define CP_COMMIT() asm volatile("cp.async.commit_group;" ::: "memory")

__device__ __forceinline__ void ldm_x4(uint32_t* r, uint32_t addr) {
    asm volatile("ldmatrix.sync.aligned.m8n8.x4.shared.b16 {%0,%1,%2,%3}, [%4];"
        : "=r"(r[0]), "=r"(r[1]), "=r"(r[2]), "=r"(r[3]) : "r"(addr));
}
__device__ __forceinline__ void ldm_x2(uint32_t* r, uint32_t addr) {
    asm volatile("ldmatrix.sync.aligned.m8n8.x2.shared.b16 {%0,%1}, [%2];"
        : "=r"(r[0]), "=r"(r[1]) : "r"(addr));
}
__device__ __forceinline__ void ldm_x2_trans(uint32_t* r, uint32_t addr) {
    asm volatile("ldmatrix.sync.aligned.m8n8.x2.trans.shared.b16 {%0,%1}, [%2];"
        : "=r"(r[0]), "=r"(r[1]) : "r"(addr));
}
__device__ __forceinline__ void mma16816(float* c, const uint32_t* a, const uint32_t* b) {
    asm volatile("mma.sync.aligned.m16n8k16.row.col.f32.bf16.bf16.f32 "
        "{%0,%1,%2,%3}, {%4,%5,%6,%7}, {%8,%9}, {%0,%1,%2,%3};"
        : "+f"(c[0]), "+f"(c[1]), "+f"(c[2]), "+f"(c[3])
        : "r"(a[0]), "r"(a[1]), "r"(a[2]), "r"(a[3]), "r"(b[0]), "r"(b[1]));
}

__device__ __forceinline__ void split2(float v, __nv_bfloat16& h, __nv_bfloat16& l) {
    h = __float2bfloat16(v);
    l = __float2bfloat16(v - __bfloat162float(h));
}
__device__ __forceinline__ uint32_t bpack(__nv_bfloat16 a, __nv_bfloat16 b) {
    __nv_bfloat162 t(a, b);
    return *reinterpret_cast<uint32_t*>(&t);
}

// ==================================================================
// Transpose per-batch [P][Q] -> [Q][P], optional fused bf16 split
// ==================================================================
__global__ void transpose_split_kernel(const float* __restrict__ in,
                                       float* __restrict__ out,
                                       __nv_bfloat16* __restrict__ hi,
                                       __nv_bfloat16* __restrict__ lo,
                                       int P, int Q)
{
    __shared__ float tile[32][33];
    const size_t bofs = (size_t)blockIdx.z * P * Q;
    in += bofs;
    int p0 = blockIdx.y * 32;
    int q0 = blockIdx.x * 32;
    int tx = threadIdx.x, ty = threadIdx.y;
    #pragma unroll
    for (int i = ty; i < 32; i += 8)
        tile[i][tx] = in[(size_t)(p0 + i) * Q + q0 + tx];
    __syncthreads();
    #pragma unroll
    for (int i = ty; i < 32; i += 8) {
        float v = tile[tx][i];
        size_t o = bofs + (size_t)(q0 + i) * P + p0 + tx;
        out[o] = v;
        if (hi) {
            __nv_bfloat16 h, l;
            split2(v, h, l);
            hi[o] = h;
            lo[o] = l;
        }
    }
}

// ==================================================================
// Batched weight prep: 10 matrices, transpose+split in ONE launch.
// ==================================================================
struct WPrepArgs {
    const float* src[10];
    int K[10];
    int N[10];
    int off[10];
};

__global__ void wprep_kernel(WPrepArgs a,
                             __nv_bfloat16* __restrict__ hi_base,
                             __nv_bfloat16* __restrict__ lo_base)
{
    __shared__ float tile[32][33];
    const int j = blockIdx.z;
    const int K = a.K[j], N = a.N[j];
    const int n0 = blockIdx.x * 32;
    const int k0 = blockIdx.y * 32;
    if (n0 >= N || k0 >= K) return;
    const float* W = a.src[j];
    __nv_bfloat16* hi = hi_base + a.off[j];
    __nv_bfloat16* lo = lo_base + a.off[j];
    int tx = threadIdx.x, ty = threadIdx.y;
    #pragma unroll
    for (int i = ty; i < 32; i += 8)
        tile[i][tx] = W[(size_t)(k0 + i) * N + n0 + tx];
    __syncthreads();
    #pragma unroll
    for (int i = ty; i < 32; i += 8) {
        float v = tile[tx][i];
        __nv_bfloat16 h, l;
        split2(v, h, l);
        size_t o = (size_t)(n0 + i) * K + k0 + tx;
        hi[o] = h;
        lo[o] = l;
    }
}

// ==================================================================
// mma.sync bf16x3 GEMM (unchanged)
// ==================================================================
#define BM 128
#define BN 256
#define BK 32
#define LDS 40
#define A_MAT (128*LDS*2)
#define B_MAT (256*LDS*2)
#define STG_BYTES (2*A_MAT + 2*B_MAT)
#define STAGES 3
#define GEMM_SMEM (STAGES*STG_BYTES)

__device__ __forceinline__ void load_tiles(uint32_t st,
    const __nv_bfloat16* ah, const __nv_bfloat16* al,
    const __nv_bfloat16* bh, const __nv_bfloat16* bl,
    int K, int k0, int tid)
{
    {
        int row = tid >> 1;
        int cb  = (tid & 1) * 32;
        uint32_t doff = (uint32_t)row * (LDS*2) + cb;
        const char* pa = (const char*)(ah + (size_t)row * K + k0) + cb;
        const char* pl = (const char*)(al + (size_t)row * K + k0) + cb;
        CP_ASYNC16(st + doff,              pa);
        CP_ASYNC16(st + doff + 16,         pa + 16);
        CP_ASYNC16(st + A_MAT + doff,      pl);
        CP_ASYNC16(st + A_MAT + doff + 16, pl + 16);
    }
    {
        int row = tid;
        uint32_t doff = (uint32_t)row * (LDS*2);
        const char* pb = (const char*)(bh + (size_t)row * K + k0);
        const char* pc = (const char*)(bl + (size_t)row * K + k0);
        uint32_t b0 = st + 2*A_MAT + doff;
        uint32_t b1 = st + 2*A_MAT + B_MAT + doff;
        #pragma unroll
        for (int c = 0; c < 4; c++) {
            CP_ASYNC16(b0 + c*16, pb + c*16);
            CP_ASYNC16(b1 + c*16, pc + c*16);
        }
    }
}

__global__ __launch_bounds__(256, 1)
void gemm_tc_kernel(int M, int N, int K,
    const __nv_bfloat16* __restrict__ Ah, const __nv_bfloat16* __restrict__ Al,
    const __nv_bfloat16* __restrict__ Bh, const __nv_bfloat16* __restrict__ Bl,
    const float* __restrict__ bias, const float* __restrict__ Rm,
    const float* __restrict__ lnG, const float* __restrict__ lnB,
    float* __restrict__ Cf,
    __nv_bfloat16* __restrict__ Ch, __nv_bfloat16* __restrict__ Cl,
    int relu)
{
    extern __shared__ char smem[];
    const uint32_t sbase = smem_u32(smem);
    const int tid  = threadIdx.x;
    const int wid  = tid >> 5;
    const int lane = tid & 31;
    const int wm = wid >> 2;
    const int wn = wid & 3;

    const int n0 = blockIdx.x * BN;
    const int m0 = blockIdx.y * BM;
    const __nv_bfloat16* ah = Ah + (size_t)m0 * K;
    const __nv_bfloat16* al = Al + (size_t)m0 * K;
    const __nv_bfloat16* bh = Bh + (size_t)n0 * K;
    const __nv_bfloat16* bl = Bl + (size_t)n0 * K;

    const int NC = K / BK;

    float acc[4][8][4];
    #pragma unroll
    for (int mt = 0; mt < 4; mt++)
        #pragma unroll
        for (int nt = 0; nt < 8; nt++)
            #pragma unroll
            for (int j = 0; j < 4; j++) acc[mt][nt][j] = 0.f;

    #pragma unroll
    for (int s = 0; s < STAGES - 1; s++) {
        if (s < NC) load_tiles(sbase + s * STG_BYTES, ah, al, bh, bl, K, s * BK, tid);
        CP_COMMIT();
    }

    const int lr16 = lane & 15;
    const int lc16 = lane >> 4;
    const int lr8  = lr16 & 7;
    const int lc8  = lr16 >> 3;

    for (int i = 0; i < NC; i++) {
        asm volatile("cp.async.wait_group %0;" :: "n"(STAGES - 2));
        __syncthreads();

        int is = i + STAGES - 1;
        if (is < NC) load_tiles(sbase + (is % STAGES) * STG_BYTES,
                                ah, al, bh, bl, K, is * BK, tid);
        CP_COMMIT();

        const uint32_t st  = sbase + (i % STAGES) * STG_BYTES;
        const uint32_t sAh = st;
        const uint32_t sAl = st + A_MAT;
        const uint32_t sBh = st + 2*A_MAT;
        const uint32_t sBl = st + 2*A_MAT + B_MAT;

        #pragma unroll
        for (int ks = 0; ks < 2; ks++) {
            uint32_t ahf[4][4], alf[4][4];
            #pragma unroll
            for (int mt = 0; mt < 4; mt++) {
                uint32_t off = ((uint32_t)(wm*64 + mt*16 + lr16) * LDS
                                + ks*16 + lc16*8) * 2;
                ldm_x4(ahf[mt], sAh + off);
                ldm_x4(alf[mt], sAl + off);
            }
            #pragma unroll
            for (int nh = 0; nh < 2; nh++) {
                uint32_t bhf[4][2], blf[4][2];
                #pragma unroll
                for (int nt = 0; nt < 4; nt++) {
                    uint32_t off = ((uint32_t)(wn*64 + nh*32 + nt*8 + lr8) * LDS
                                    + ks*16 + lc8*8) * 2;
                    ldm_x2(bhf[nt], sBh + off);
                    ldm_x2(blf[nt], sBl + off);
                }
                #pragma unroll
                for (int mt = 0; mt < 4; mt++)
                    #pragma unroll
                    for (int nt = 0; nt < 4; nt++) {
                        float* c = acc[mt][nh*4 + nt];
                        mma16816(c, ahf[mt], bhf[nt]);
                        mma16816(c, ahf[mt], blf[nt]);
                        mma16816(c, alf[mt], bhf[nt]);
                    }
            }
        }
    }

    // ---------------- Epilogue ----------------
    const int rit = lane >> 2;
    const int cit = (lane & 3) * 2;

    #pragma unroll
    for (int mt = 0; mt < 4; mt++) {
        #pragma unroll
        for (int nt = 0; nt < 8; nt++) {
            int gc = n0 + wn*64 + nt*8 + cit;
            float* c = acc[mt][nt];
            if (bias) {
                float2 bb = *(const float2*)(bias + gc);
                c[0] += bb.x; c[1] += bb.y; c[2] += bb.x; c[3] += bb.y;
            }
            if (Rm) {
                int gr0 = m0 + wm*64 + mt*16 + rit;
                float2 r0 = *(const float2*)(Rm + (size_t)gr0 * N + gc);
                float2 r1 = *(const float2*)(Rm + (size_t)(gr0 + 8) * N + gc);
                c[0] += r0.x; c[1] += r0.y; c[2] += r1.x; c[3] += r1.y;
            }
            if (relu) {
                c[0] = fmaxf(c[0], 0.f); c[1] = fmaxf(c[1], 0.f);
                c[2] = fmaxf(c[2], 0.f); c[3] = fmaxf(c[3], 0.f);
            }
        }
    }

    if (lnG) {
        float2* red = (float2*)smem;
        __syncthreads();
        #pragma unroll
        for (int mt = 0; mt < 4; mt++) {
            float s0 = 0.f, q0 = 0.f, s1 = 0.f, q1 = 0.f;
            #pragma unroll
            for (int nt = 0; nt < 8; nt++) {
                float* c = acc[mt][nt];
                s0 += c[0] + c[1]; q0 += c[0]*c[0] + c[1]*c[1];
                s1 += c[2] + c[3]; q1 += c[2]*c[2] + c[3]*c[3];
            }
            #pragma unroll
            for (int o = 1; o < 4; o <<= 1) {
                s0 += __shfl_xor_sync(0xffffffffu, s0, o);
                q0 += __shfl_xor_sync(0xffffffffu, q0, o);
                s1 += __shfl_xor_sync(0xffffffffu, s1, o);
                q1 += __shfl_xor_sync(0xffffffffu, q1, o);
            }
            if ((lane & 3) == 0) {
                int r0 = wm*64 + mt*16 + rit;
                red[r0*4 + wn]       = make_float2(s0, q0);
                red[(r0 + 8)*4 + wn] = make_float2(s1, q1);
            }
        }
        __syncthreads();
        #pragma unroll
        for (int mt = 0; mt < 4; mt++) {
            int r0 = wm*64 + mt*16 + rit;
            float S0 = 0.f, Q0 = 0.f, S1 = 0.f, Q1 = 0.f;
            #pragma unroll
            for (int w = 0; w < 4; w++) {
                float2 p0 = red[r0*4 + w];
                float2 p1 = red[(r0 + 8)*4 + w];
                S0 += p0.x; Q0 += p0.y;
                S1 += p1.x; Q1 += p1.y;
            }
            float mu0 = S0 * (1.0f/256.0f);
            float mu1 = S1 * (1.0f/256.0f);
            float rs0 = rsqrtf(Q0 * (1.0f/256.0f) - mu0*mu0 + 1e-5f);
            float rs1 = rsqrtf(Q1 * (1.0f/256.0f) - mu1*mu1 + 1e-5f);
            #pragma unroll
            for (int nt = 0; nt < 8; nt++) {
                int gc = wn*64 + nt*8 + cit;
                float2 g2 = *(const float2*)(lnG + gc);
                float2 b2 = *(const float2*)(lnB + gc);
                float* c = acc[mt][nt];
                c[0] = (c[0] - mu0) * rs0 * g2.x + b2.x;
                c[1] = (c[1] - mu0) * rs0 * g2.y + b2.y;
                c[2] = (c[2] - mu1) * rs1 * g2.x + b2.x;
                c[3] = (c[3] - mu1) * rs1 * g2.y + b2.y;
            }
        }
    }

    #pragma unroll
    for (int mt = 0; mt < 4; mt++) {
        #pragma unroll
        for (int nt = 0; nt < 8; nt++) {
            int gr0 = m0 + wm*64 + mt*16 + rit;
            int gc  = n0 + wn*64 + nt*8 + cit;
            size_t o0 = (size_t)gr0 * N + gc;
            size_t o1 = (size_t)(gr0 + 8) * N + gc;
            float* c = acc[mt][nt];
            if (Cf) {
                *(float2*)(Cf + o0) = make_float2(c[0], c[1]);
                *(float2*)(Cf + o1) = make_float2(c[2], c[3]);
            }
            if (Ch) {
                __nv_bfloat16 h0, h1, h2, h3, l0, l1, l2, l3;
                split2(c[0], h0, l0); split2(c[1], h1, l1);
                split2(c[2], h2, l2); split2(c[3], h3, l3);
                *(__nv_bfloat162*)(Ch + o0) = __nv_bfloat162(h0, h1);
                *(__nv_bfloat162*)(Ch + o1) = __nv_bfloat162(h2, h3);
                *(__nv_bfloat162*)(Cl + o0) = __nv_bfloat162(l0, l1);
                *(__nv_bfloat162*)(Cl + o1) = __nv_bfloat162(l2, l3);
            }
        }
    }
}

// ==================================================================
// Windowed attention — tensor-core FA2-style, 2 HEADS PER BLOCK.
// Block = (window, head-pair), 256 threads (8 warps; 4/head).
// Per-row loads are 64 elems = 128B contiguous & 128B-aligned ->
// full line utilization (keeps round-13's DRAM fix) while regs
// (78 x 256 = 20K/CTA) allow 3 CTAs/SM (restores occupancy).
// Row stride 144B: rows step 16B mod 128 -> ldmatrix conflict-free.
// ==================================================================
#define HG 2                     /* heads per block */
#define ALD2 72                  /* smem row, elements (64 + 8 pad) */
#define SM_MAT (LWIN*ALD2)       /* elements per matrix */
#define ATTN_SMEM (6*SM_MAT*2)   /* bytes = 55296 */

__global__ __launch_bounds__(256)
void win_attn_kernel(const __nv_bfloat16* __restrict__ Qhp,
                     const __nv_bfloat16* __restrict__ Qlp, int qs,
                     const __nv_bfloat16* __restrict__ Khp,
                     const __nv_bfloat16* __restrict__ Klp,
                     const __nv_bfloat16* __restrict__ Vhp,
                     const __nv_bfloat16* __restrict__ Vlp, int kvs,
                     __nv_bfloat16* __restrict__ Oh, __nv_bfloat16* __restrict__ Ol,
                     int qH, int qW, int kH, int kW, int ks)
{
    extern __shared__ __nv_bfloat16 sm[];
    __nv_bfloat16 *SQh = sm,            *SQl = sm + SM_MAT,
                  *SKh = sm + 2*SM_MAT, *SKl = sm + 3*SM_MAT,
                  *SVh = sm + 4*SM_MAT, *SVl = sm + 5*SM_MAT;

    const int tid  = threadIdx.x;
    const int grp  = blockIdx.y;          // head pair (0..3)
    const int win  = blockIdx.x;
    const int nWw  = qW / WS;
    const int wpb  = (qH / WS) * nWw;
    const int n    = win / wpb;
    const int r    = win % wpb;
    const int wh   = r / nWw, ww = r % nWw;

    const size_t qbase = (size_t)n * qH * qW;
    const size_t kbase = (size_t)n * kH * kW;
    const int co = grp * (HG * DH);       // 64-elem slice base

    // ---- load: 64 rows x 64 elems per matrix; 8 chunks/row ----
    #pragma unroll
    for (int it = 0; it < 2; it++) {
        int idx = tid + it * 256;
        int row = idx >> 3;               // 0..63
        int c8  = (idx & 7) * 8;          // element offset in 64-wide slice
        int i = row >> 3, j = row & 7;
        size_t qt = qbase + (size_t)(wh * WS + i) * qW + (ww * WS + j);
        int ki = (wh * ks + i) % kH;
        int kj = (ww * ks + j) % kW;
        size_t kt = kbase + (size_t)ki * kW + kj;

        *(uint4*)&SQh[row*ALD2 + c8] = *(const uint4*)(Qhp + qt * qs + co + c8);
        *(uint4*)&SQl[row*ALD2 + c8] = *(const uint4*)(Qlp + qt * qs + co + c8);
        *(uint4*)&SKh[row*ALD2 + c8] = *(const uint4*)(Khp + kt * kvs + co + c8);
        *(uint4*)&SKl[row*ALD2 + c8] = *(const uint4*)(Klp + kt * kvs + co + c8);
        *(uint4*)&SVh[row*ALD2 + c8] = *(const uint4*)(Vhp + kt * kvs + co + c8);
        *(uint4*)&SVl[row*ALD2 + c8] = *(const uint4*)(Vlp + kt * kvs + co + c8);
    }
    __syncthreads();

    const int wid  = tid >> 5;
    const int lane = tid & 31;
    const int hg   = wid >> 2;            // head within pair (0..1)
    const int w4   = wid & 3;             // warp within head
    const int hb   = hg * DH;             // column base within smem row
    const int lr16 = lane & 15;
    const int lc16 = lane >> 4;
    const int lr8  = lr16 & 7;
    const int lc8  = lr16 >> 3;

    const uint32_t aQh = smem_u32(SQh), aQl = smem_u32(SQl);
    const uint32_t aKh = smem_u32(SKh), aKl = smem_u32(SKl);
    const uint32_t aVh = smem_u32(SVh), aVl = smem_u32(SVl);

    // ---- S = Q @ K^T (bf16x3, fp32 accum) ----
    float sacc[8][4];
    #pragma unroll
    for (int nt = 0; nt < 8; nt++)
        #pragma unroll
        for (int j = 0; j < 4; j++) sacc[nt][j] = 0.f;

    #pragma unroll
    for (int k2 = 0; k2 < 2; k2++) {
        uint32_t qh[4], ql[4];
        uint32_t offA = ((uint32_t)(w4*16 + lr16) * ALD2 + hb + k2*16 + lc16*8) * 2;
        ldm_x4(qh, aQh + offA);
        ldm_x4(ql, aQl + offA);
        #pragma unroll
        for (int nt = 0; nt < 8; nt++) {
            uint32_t kh[2], kl[2];
            uint32_t offB = ((uint32_t)(nt*8 + lr8) * ALD2 + hb + k2*16 + lc8*8) * 2;
            ldm_x2(kh, aKh + offB);
            ldm_x2(kl, aKl + offB);
            mma16816(sacc[nt], qh, kh);
            mma16816(sacc[nt], qh, kl);
            mma16816(sacc[nt], ql, kh);
        }
    }

    // ---- exp (max-free) + row sums ----
    const float SC = 0.17677669529663687f;
    float s0 = 0.f, s1 = 0.f;
    #pragma unroll
    for (int nt = 0; nt < 8; nt++) {
        sacc[nt][0] = __expf(sacc[nt][0] * SC);
        sacc[nt][1] = __expf(sacc[nt][1] * SC);
        sacc[nt][2] = __expf(sacc[nt][2] * SC);
        sacc[nt][3] = __expf(sacc[nt][3] * SC);
        s0 += sacc[nt][0] + sacc[nt][1];
        s1 += sacc[nt][2] + sacc[nt][3];
    }
    s0 += __shfl_xor_sync(0xffffffffu, s0, 1);
    s0 += __shfl_xor_sync(0xffffffffu, s0, 2);
    s1 += __shfl_xor_sync(0xffffffffu, s1, 1);
    s1 += __shfl_xor_sync(0xffffffffu, s1, 2);
    const float inv0 = 1.0f / s0;
    const float inv1 = 1.0f / s1;

    // ---- O = P @ V (bf16x3; P accum->A-fragment identity) ----
    float oacc[4][4];
    #pragma unroll
    for (int nt = 0; nt < 4; nt++)
        #pragma unroll
        for (int j = 0; j < 4; j++) oacc[nt][j] = 0.f;

    #pragma unroll
    for (int kk = 0; kk < 4; kk++) {
        uint32_t ph[4], pl[4];
        #pragma unroll
        for (int h2 = 0; h2 < 2; h2++) {
            float* sp = sacc[kk*2 + h2];
            #pragma unroll
            for (int g = 0; g < 2; g++) {
                float p0 = sp[g*2], p1 = sp[g*2 + 1];
                __nv_bfloat16 hh0 = __float2bfloat16(p0);
                __nv_bfloat16 hh1 = __float2bfloat16(p1);
                ph[h2*2 + g] = bpack(hh0, hh1);
                pl[h2*2 + g] = bpack(
                    __float2bfloat16(p0 - __bfloat162float(hh0)),
                    __float2bfloat16(p1 - __bfloat162float(hh1)));
            }
        }
        #pragma unroll
        for (int nt = 0; nt < 4; nt++) {
            uint32_t vh[2], vl[2];
            uint32_t offV = ((uint32_t)(kk*16 + lr16) * ALD2 + hb + nt*8) * 2;
            ldm_x2_trans(vh, aVh + offV);
            ldm_x2_trans(vl, aVl + offV);
            mma16816(oacc[nt], ph, vh);
            mma16816(oacc[nt], ph, vl);
            mma16816(oacc[nt], pl, vh);
        }
    }

    // ---- normalize + store bf16 hi/lo (stride C_DIM) ----
    const int cit = (lane & 3) * 2;
    const int oc  = co + hb;              // output column base
    int r0 = w4*16 + (lane >> 2);
    int r1 = r0 + 8;
    int i0 = r0 >> 3, j0 = r0 & 7;
    int i1 = r1 >> 3, j1 = r1 & 7;
    size_t t0 = qbase + (size_t)(wh * WS + i0) * qW + (ww * WS + j0);
    size_t t1 = qbase + (size_t)(wh * WS + i1) * qW + (ww * WS + j1);
    size_t ob0 = t0 * C_DIM + oc + cit;
    size_t ob1 = t1 * C_DIM + oc + cit;

    #pragma unroll
    for (int nt = 0; nt < 4; nt++) {
        float v0 = oacc[nt][0] * inv0;
        float v1 = oacc[nt][1] * inv0;
        float v2 = oacc[nt][2] * inv1;
        float v3 = oacc[nt][3] * inv1;
        __nv_bfloat16 h0, h1, h2, h3, l0, l1, l2, l3;
        split2(v0, h0, l0); split2(v1, h1, l1);
        split2(v2, h2, l2); split2(v3, h3, l3);
        *(__nv_bfloat162*)(Oh + ob0 + nt*8) = __nv_bfloat162(h0, h1);
        *(__nv_bfloat162*)(Ol + ob0 + nt*8) = __nv_bfloat162(l0, l1);
        *(__nv_bfloat162*)(Oh + ob1 + nt*8) = __nv_bfloat162(h2, h3);
        *(__nv_bfloat162*)(Ol + ob1 + nt*8) = __nv_bfloat162(l2, l3);
    }
}

// ==================================================================
// 4x4 average pool (NHWC), fp32 + bf16 hi/lo out
// ==================================================================
__global__ __launch_bounds__(256)
void avgpool_kernel(const float* __restrict__ in, float* __restrict__ outf,
                    __nv_bfloat16* __restrict__ outh, __nv_bfloat16* __restrict__ outl)
{
    int t = blockIdx.x;
    int c = threadIdx.x;
    int n = t / (H1 * W1);
    int r = t % (H1 * W1);
    int oh = r / W1, ow = r % W1;
    float s = 0.f;
    #pragma unroll
    for (int dy = 0; dy < 4; dy++)
        #pragma unroll
        for (int dx = 0; dx < 4; dx++) {
            size_t tok = (size_t)n * H0 * W0 + (size_t)(oh * 4 + dy) * W0 + (ow * 4 + dx);
            s += in[tok * C_DIM + c];
        }
    s *= (1.0f / 16.0f);
    size_t o = (size_t)t * C_DIM + c;
    outf[o] = s;
    __nv_bfloat16 h, l;
    split2(s, h, l);
    outh[o] = h;
    outl[o] = l;
}

// ==================================================================
// Host side
// ==================================================================
#define WT_QKV  0
#define WT_SAF  196608
#define WT_CAQ  262144
#define WT_CAKV 327680
#define WT_CAF  458752
#define WT_W1   524288
#define WT_W2   786432

extern "C" void kernel_launch(void* const* d_in, const int* in_sizes, int n_in,
                              void* d_out, int out_size)
{
    const float* x       = (const float*)d_in[0];
    const float* sa_wq   = (const float*)d_in[1];
    const float* sa_wk   = (const float*)d_in[2];
    const float* sa_wv   = (const float*)d_in[3];
    const float* sa_wf   = (const float*)d_in[4];
    const float* sa_bf   = (const float*)d_in[5];
    const float* ca_wq   = (const float*)d_in[6];
    const float* ca_wk   = (const float*)d_in[7];
    const float* ca_wv   = (const float*)d_in[8];
    const float* ca_wf   = (const float*)d_in[9];
    const float* ca_bf   = (const float*)d_in[10];
    const float* ln_self_g = (const float*)d_in[11];
    const float* ln_self_b = (const float*)d_in[12];
    const float* ln_cross_g= (const float*)d_in[13];
    const float* ln_cross_b= (const float*)d_in[14];
    const float* ffn_w1  = (const float*)d_in[15];
    const float* ffn_b1  = (const float*)d_in[16];
    const float* ffn_w2  = (const float*)d_in[17];
    const float* ffn_b2  = (const float*)d_in[18];
    const float* ln_out_g= (const float*)d_in[19];
    const float* ln_out_b= (const float*)d_in[20];
    float* out = (float*)d_out;

    float *bufA, *bufB, *bufL0;
    __nv_bfloat16 *qkvh, *qkvl, *ash, *asl, *l0h, *l0l, *fh, *fl, *wth, *wtl;
    cudaGetSymbolAddress((void**)&bufA,  g_bufA);
    cudaGetSymbolAddress((void**)&bufB,  g_bufB);
    cudaGetSymbolAddress((void**)&bufL0, g_bufL0);
    cudaGetSymbolAddress((void**)&qkvh,  g_qkvh);
    cudaGetSymbolAddress((void**)&qkvl,  g_qkvl);
    cudaGetSymbolAddress((void**)&ash,   g_ash);
    cudaGetSymbolAddress((void**)&asl,   g_asl);
    cudaGetSymbolAddress((void**)&l0h,   g_l0h);
    cudaGetSymbolAddress((void**)&l0l,   g_l0l);
    cudaGetSymbolAddress((void**)&fh,    g_fh);
    cudaGetSymbolAddress((void**)&fl,    g_fl);
    cudaGetSymbolAddress((void**)&wth,   g_wth);
    cudaGetSymbolAddress((void**)&wtl,   g_wtl);

    cudaFuncSetAttribute(gemm_tc_kernel,
                         cudaFuncAttributeMaxDynamicSharedMemorySize, GEMM_SMEM);
    cudaFuncSetAttribute(win_attn_kernel,
                         cudaFuncAttributeMaxDynamicSharedMemorySize, ATTN_SMEM);

    dim3 tb(32, 8);

    auto gemm = [&](int M, int N, int K,
                    const __nv_bfloat16* Ahp, const __nv_bfloat16* Alp,
                    const __nv_bfloat16* Bhp, const __nv_bfloat16* Blp,
                    const float* bias, const float* resid,
                    const float* lnG, const float* lnB,
                    float* Cf, __nv_bfloat16* Ch, __nv_bfloat16* Cl, int relu) {
        dim3 grid(N / BN, M / BM);
        gemm_tc_kernel<<<grid, 256, GEMM_SMEM>>>(M, N, K, Ahp, Alp, Bhp, Blp,
                                                 bias, resid, lnG, lnB,
                                                 Cf, Ch, Cl, relu);
    };

    // --- batched weight prep (one launch) ---
    {
        WPrepArgs a;
        const float* srcs[10] = {sa_wq, sa_wk, sa_wv, sa_wf, ca_wq,
                                 ca_wk, ca_wv, ca_wf, ffn_w1, ffn_w2};
        int Ks[10]  = {256,256,256,256,256,256,256,256,256,1024};
        int Ns[10]  = {256,256,256,256,256,256,256,256,1024,256};
        int offs[10] = {WT_QKV, WT_QKV + 65536, WT_QKV + 131072, WT_SAF,
                        WT_CAQ, WT_CAKV, WT_CAKV + 65536, WT_CAF,
                        WT_W1, WT_W2};
        for (int j = 0; j < 10; j++) {
            a.src[j] = srcs[j]; a.K[j] = Ks[j]; a.N[j] = Ns[j]; a.off[j] = offs[j];
        }
        wprep_kernel<<<dim3(32, 32, 10), tb>>>(a, wth, wtl);
    }

    // 0. NCHW -> NHWC (+split)
    transpose_split_kernel<<<dim3(H0*W0/32, C_DIM/32, NB), tb>>>(x, bufA, ash, asl,
                                                                 C_DIM, H0*W0);

    // 1. Self-attention level 0
    gemm(T0, 768, 256, ash, asl, wth + WT_QKV, wtl + WT_QKV,
         nullptr, nullptr, nullptr, nullptr, nullptr, qkvh, qkvl, 0);
    win_attn_kernel<<<dim3(NB*16*16, NHEADS/HG), 256, ATTN_SMEM>>>(
        qkvh, qkvl, 768, qkvh + 256, qkvl + 256, qkvh + 512, qkvl + 512, 768,
        ash, asl, H0, W0, H0, W0, WS);
    gemm(T0, 256, 256, ash, asl, wth + WT_SAF, wtl + WT_SAF,
         sa_bf, bufA, ln_self_g, ln_self_b, bufL0, l0h, l0l, 0);

    // 2. avgpool
    avgpool_kernel<<<T1, 256>>>(bufL0, bufB, ash, asl);

    // 3. Self-attention level 1
    gemm(T1, 768, 256, ash, asl, wth + WT_QKV, wtl + WT_QKV,
         nullptr, nullptr, nullptr, nullptr, nullptr, qkvh, qkvl, 0);
    win_attn_kernel<<<dim3(NB*4*4, NHEADS/HG), 256, ATTN_SMEM>>>(
        qkvh, qkvl, 768, qkvh + 256, qkvl + 256, qkvh + 512, qkvl + 512, 768,
        ash, asl, H1, W1, H1, W1, WS);
    gemm(T1, 256, 256, ash, asl, wth + WT_SAF, wtl + WT_SAF,
         sa_bf, bufB, ln_self_g, ln_self_b, nullptr, ash, asl, 0);

    // 4. Cross-attention
    gemm(T1, 512, 256, ash, asl, wth + WT_CAKV, wtl + WT_CAKV,
         nullptr, nullptr, nullptr, nullptr, nullptr, qkvh, qkvl, 0);
    gemm(T0, 256, 256, l0h, l0l, wth + WT_CAQ, wtl + WT_CAQ,
         nullptr, nullptr, nullptr, nullptr, nullptr, fh, fl, 0);
    win_attn_kernel<<<dim3(NB*16*16, NHEADS/HG), 256, ATTN_SMEM>>>(
        fh, fl, 256, qkvh, qkvl, qkvh + 256, qkvl + 256, 512,
        ash, asl, H0, W0, H1, W1, 2);
    gemm(T0, 256, 256, ash, asl, wth + WT_CAF, wtl + WT_CAF,
         ca_bf, bufL0, ln_cross_g, ln_cross_b, bufB, ash, asl, 0);

    // 5. FFN (+fused final LN on FFN2)
    gemm(T0, 1024, 256, ash, asl, wth + WT_W1, wtl + WT_W1,
         ffn_b1, nullptr, nullptr, nullptr, nullptr, fh, fl, 1);
    gemm(T0, 256, 1024, fh, fl, wth + WT_W2, wtl + WT_W2,
         ffn_b2, bufB, ln_out_g, ln_out_b, bufL0, nullptr, nullptr, 0);

    // 6. NHWC -> NCHW
    transpose_split_kernel<<<dim3(C_DIM/32, H0*W0/32, NB), tb>>>(bufL0, out,
        nullptr, nullptr, H0*W0, C_DIM);
}

// round 15
// speedup vs baseline: 1.1727x; 1.1454x over previous
#include <cuda_runtime.h>
#include <cuda_bf16.h>
#include <cuda_fp16.h>
#include <cstdint>

#define C_DIM 256
#define DF_DIM 1024
#define NB 8
#define H0 128
#define W0 128
#define T0 (NB*H0*W0)      /* 131072 */
#define H1 32
#define W1 32
#define T1 (NB*H1*W1)      /* 8192 */
#define NHEADS 8
#define DH 32
#define WS 8
#define LWIN 64

// ==================================================================
// Scratch (device globals — allocation-free)
// ==================================================================
__device__ float g_bufA  [(size_t)T0*C_DIM];
__device__ float g_bufB  [(size_t)T0*C_DIM];
__device__ float g_bufL0 [(size_t)T0*C_DIM];
__device__ __nv_bfloat16 g_qkvh[(size_t)T0*768];
__device__ __nv_bfloat16 g_qkvl[(size_t)T0*768];
__device__ __nv_bfloat16 g_ash[(size_t)T0*DF_DIM];
__device__ __nv_bfloat16 g_asl[(size_t)T0*DF_DIM];
__device__ __nv_bfloat16 g_l0h[(size_t)T0*C_DIM];
__device__ __nv_bfloat16 g_l0l[(size_t)T0*C_DIM];
__device__ __nv_bfloat16 g_fh [(size_t)T0*DF_DIM];
__device__ __nv_bfloat16 g_fl [(size_t)T0*DF_DIM];
__device__ __nv_bfloat16 g_wth[1048576];
__device__ __nv_bfloat16 g_wtl[1048576];
__device__ __half g_wph[524288];   /* fp16 weights: w1 [1024,256], w2 [256,1024] */
__device__ __half g_wpl[524288];

// ==================================================================
// PTX helpers
// ==================================================================
__device__ __forceinline__ uint32_t smem_u32(const void* p) {
    uint32_t a;
    asm("{ .reg .u64 t; cvta.to.shared.u64 t, %1; cvt.u32.u64 %0, t; }"
        : "=r"(a) : "l"(p));
    return a;
}

#define CP_ASYNC16(dst, src) \
    asm volatile("cp.async.cg.shared.global [%0], [%1], 16;" :: "r"(dst), "l"(src) : "memory")
#define CP_COMMIT() asm volatile("cp.async.commit_group;" ::: "memory")

__device__ __forceinline__ void ldm_x4(uint32_t* r, uint32_t addr) {
    asm volatile("ldmatrix.sync.aligned.m8n8.x4.shared.b16 {%0,%1,%2,%3}, [%4];"
        : "=r"(r[0]), "=r"(r[1]), "=r"(r[2]), "=r"(r[3]) : "r"(addr));
}
__device__ __forceinline__ void ldm_x2(uint32_t* r, uint32_t addr) {
    asm volatile("ldmatrix.sync.aligned.m8n8.x2.shared.b16 {%0,%1}, [%2];"
        : "=r"(r[0]), "=r"(r[1]) : "r"(addr));
}
__device__ __forceinline__ void ldm_x2_trans(uint32_t* r, uint32_t addr) {
    asm volatile("ldmatrix.sync.aligned.m8n8.x2.trans.shared.b16 {%0,%1}, [%2];"
        : "=r"(r[0]), "=r"(r[1]) : "r"(addr));
}
__device__ __forceinline__ void mma16816(float* c, const uint32_t* a, const uint32_t* b) {
    asm volatile("mma.sync.aligned.m16n8k16.row.col.f32.bf16.bf16.f32 "
        "{%0,%1,%2,%3}, {%4,%5,%6,%7}, {%8,%9}, {%0,%1,%2,%3};"
        : "+f"(c[0]), "+f"(c[1]), "+f"(c[2]), "+f"(c[3])
        : "r"(a[0]), "r"(a[1]), "r"(a[2]), "r"(a[3]), "r"(b[0]), "r"(b[1]));
}
__device__ __forceinline__ void mma16816h(float* c, const uint32_t* a, const uint32_t* b) {
    asm volatile("mma.sync.aligned.m16n8k16.row.col.f32.f16.f16.f32 "
        "{%0,%1,%2,%3}, {%4,%5,%6,%7}, {%8,%9}, {%0,%1,%2,%3};"
        : "+f"(c[0]), "+f"(c[1]), "+f"(c[2]), "+f"(c[3])
        : "r"(a[0]), "r"(a[1]), "r"(a[2]), "r"(a[3]), "r"(b[0]), "r"(b[1]));
}

__device__ __forceinline__ void split2(float v, __nv_bfloat16& h, __nv_bfloat16& l) {
    h = __float2bfloat16(v);
    l = __float2bfloat16(v - __bfloat162float(h));
}
__device__ __forceinline__ uint32_t bpack(__nv_bfloat16 a, __nv_bfloat16 b) {
    __nv_bfloat162 t(a, b);
    return *reinterpret_cast<uint32_t*>(&t);
}

// ==================================================================
// Transpose per-batch [P][Q] -> [Q][P], optional fused bf16 split
// ==================================================================
__global__ void transpose_split_kernel(const float* __restrict__ in,
                                       float* __restrict__ out,
                                       __nv_bfloat16* __restrict__ hi,
                                       __nv_bfloat16* __restrict__ lo,
                                       int P, int Q)
{
    __shared__ float tile[32][33];
    const size_t bofs = (size_t)blockIdx.z * P * Q;
    in += bofs;
    int p0 = blockIdx.y * 32;
    int q0 = blockIdx.x * 32;
    int tx = threadIdx.x, ty = threadIdx.y;
    #pragma unroll
    for (int i = ty; i < 32; i += 8)
        tile[i][tx] = in[(size_t)(p0 + i) * Q + q0 + tx];
    __syncthreads();
    #pragma unroll
    for (int i = ty; i < 32; i += 8) {
        float v = tile[tx][i];
        size_t o = bofs + (size_t)(q0 + i) * P + p0 + tx;
        out[o] = v;
        if (hi) {
            __nv_bfloat16 h, l;
            split2(v, h, l);
            hi[o] = h;
            lo[o] = l;
        }
    }
}

// ==================================================================
// Batched weight prep (bf16): 8 matrices, transpose+split, one launch
// ==================================================================
struct WPrepArgs {
    const float* src[8];
    int K[8];
    int N[8];
    int off[8];
};

__global__ void wprep_kernel(WPrepArgs a,
                             __nv_bfloat16* __restrict__ hi_base,
                             __nv_bfloat16* __restrict__ lo_base)
{
    __shared__ float tile[32][33];
    const int j = blockIdx.z;
    const int K = a.K[j], N = a.N[j];
    const int n0 = blockIdx.x * 32;
    const int k0 = blockIdx.y * 32;
    if (n0 >= N || k0 >= K) return;
    const float* W = a.src[j];
    __nv_bfloat16* hi = hi_base + a.off[j];
    __nv_bfloat16* lo = lo_base + a.off[j];
    int tx = threadIdx.x, ty = threadIdx.y;
    #pragma unroll
    for (int i = ty; i < 32; i += 8)
        tile[i][tx] = W[(size_t)(k0 + i) * N + n0 + tx];
    __syncthreads();
    #pragma unroll
    for (int i = ty; i < 32; i += 8) {
        float v = tile[tx][i];
        __nv_bfloat16 h, l;
        split2(v, h, l);
        size_t o = (size_t)(n0 + i) * K + k0 + tx;
        hi[o] = h;
        lo[o] = l;
    }
}

// fp16 weight prep: job 0 = ffn_w1 (K=256,N=1024), job 1 = ffn_w2 (K=1024,N=256)
__global__ void wprep_h_kernel(const float* __restrict__ w1,
                               const float* __restrict__ w2,
                               __half* __restrict__ hi_base,
                               __half* __restrict__ lo_base)
{
    __shared__ float tile[32][33];
    const int j = blockIdx.z;
    const float* W = j ? w2 : w1;
    const int K = j ? 1024 : 256;
    const int N = j ? 256 : 1024;
    const int off = j ? 262144 : 0;
    const int n0 = blockIdx.x * 32;
    const int k0 = blockIdx.y * 32;
    if (n0 >= N || k0 >= K) return;
    __half* hi = hi_base + off;
    __half* lo = lo_base + off;
    int tx = threadIdx.x, ty = threadIdx.y;
    #pragma unroll
    for (int i = ty; i < 32; i += 8)
        tile[i][tx] = W[(size_t)(k0 + i) * N + n0 + tx];
    __syncthreads();
    #pragma unroll
    for (int i = ty; i < 32; i += 8) {
        float v = tile[tx][i];
        __half h = __float2half(v);
        __half l = __float2half(v - __half2float(h));
        size_t o = (size_t)(n0 + i) * K + k0 + tx;
        hi[o] = h;
        lo[o] = l;
    }
}

// ==================================================================
// mma.sync bf16x3 GEMM (adds optional fp16-single output Cp)
// ==================================================================
#define BM 128
#define BN 256
#define BK 32
#define LDS 40
#define A_MAT (128*LDS*2)
#define B_MAT (256*LDS*2)
#define STG_BYTES (2*A_MAT + 2*B_MAT)
#define STAGES 3
#define GEMM_SMEM (STAGES*STG_BYTES)

__device__ __forceinline__ void load_tiles(uint32_t st,
    const __nv_bfloat16* ah, const __nv_bfloat16* al,
    const __nv_bfloat16* bh, const __nv_bfloat16* bl,
    int K, int k0, int tid)
{
    {
        int row = tid >> 1;
        int cb  = (tid & 1) * 32;
        uint32_t doff = (uint32_t)row * (LDS*2) + cb;
        const char* pa = (const char*)(ah + (size_t)row * K + k0) + cb;
        const char* pl = (const char*)(al + (size_t)row * K + k0) + cb;
        CP_ASYNC16(st + doff,              pa);
        CP_ASYNC16(st + doff + 16,         pa + 16);
        CP_ASYNC16(st + A_MAT + doff,      pl);
        CP_ASYNC16(st + A_MAT + doff + 16, pl + 16);
    }
    {
        int row = tid;
        uint32_t doff = (uint32_t)row * (LDS*2);
        const char* pb = (const char*)(bh + (size_t)row * K + k0);
        const char* pc = (const char*)(bl + (size_t)row * K + k0);
        uint32_t b0 = st + 2*A_MAT + doff;
        uint32_t b1 = st + 2*A_MAT + B_MAT + doff;
        #pragma unroll
        for (int c = 0; c < 4; c++) {
            CP_ASYNC16(b0 + c*16, pb + c*16);
            CP_ASYNC16(b1 + c*16, pc + c*16);
        }
    }
}

__global__ __launch_bounds__(256, 1)
void gemm_tc_kernel(int M, int N, int K,
    const __nv_bfloat16* __restrict__ Ah, const __nv_bfloat16* __restrict__ Al,
    const __nv_bfloat16* __restrict__ Bh, const __nv_bfloat16* __restrict__ Bl,
    const float* __restrict__ bias, const float* __restrict__ Rm,
    const float* __restrict__ lnG, const float* __restrict__ lnB,
    float* __restrict__ Cf,
    __nv_bfloat16* __restrict__ Ch, __nv_bfloat16* __restrict__ Cl,
    __half* __restrict__ Cp,
    int relu)
{
    extern __shared__ char smem[];
    const uint32_t sbase = smem_u32(smem);
    const int tid  = threadIdx.x;
    const int wid  = tid >> 5;
    const int lane = tid & 31;
    const int wm = wid >> 2;
    const int wn = wid & 3;

    const int n0 = blockIdx.x * BN;
    const int m0 = blockIdx.y * BM;
    const __nv_bfloat16* ah = Ah + (size_t)m0 * K;
    const __nv_bfloat16* al = Al + (size_t)m0 * K;
    const __nv_bfloat16* bh = Bh + (size_t)n0 * K;
    const __nv_bfloat16* bl = Bl + (size_t)n0 * K;

    const int NC = K / BK;

    float acc[4][8][4];
    #pragma unroll
    for (int mt = 0; mt < 4; mt++)
        #pragma unroll
        for (int nt = 0; nt < 8; nt++)
            #pragma unroll
            for (int j = 0; j < 4; j++) acc[mt][nt][j] = 0.f;

    #pragma unroll
    for (int s = 0; s < STAGES - 1; s++) {
        if (s < NC) load_tiles(sbase + s * STG_BYTES, ah, al, bh, bl, K, s * BK, tid);
        CP_COMMIT();
    }

    const int lr16 = lane & 15;
    const int lc16 = lane >> 4;
    const int lr8  = lr16 & 7;
    const int lc8  = lr16 >> 3;

    for (int i = 0; i < NC; i++) {
        asm volatile("cp.async.wait_group %0;" :: "n"(STAGES - 2));
        __syncthreads();

        int is = i + STAGES - 1;
        if (is < NC) load_tiles(sbase + (is % STAGES) * STG_BYTES,
                                ah, al, bh, bl, K, is * BK, tid);
        CP_COMMIT();

        const uint32_t st  = sbase + (i % STAGES) * STG_BYTES;
        const uint32_t sAh = st;
        const uint32_t sAl = st + A_MAT;
        const uint32_t sBh = st + 2*A_MAT;
        const uint32_t sBl = st + 2*A_MAT + B_MAT;

        #pragma unroll
        for (int ks = 0; ks < 2; ks++) {
            uint32_t ahf[4][4], alf[4][4];
            #pragma unroll
            for (int mt = 0; mt < 4; mt++) {
                uint32_t off = ((uint32_t)(wm*64 + mt*16 + lr16) * LDS
                                + ks*16 + lc16*8) * 2;
                ldm_x4(ahf[mt], sAh + off);
                ldm_x4(alf[mt], sAl + off);
            }
            #pragma unroll
            for (int nh = 0; nh < 2; nh++) {
                uint32_t bhf[4][2], blf[4][2];
                #pragma unroll
                for (int nt = 0; nt < 4; nt++) {
                    uint32_t off = ((uint32_t)(wn*64 + nh*32 + nt*8 + lr8) * LDS
                                    + ks*16 + lc8*8) * 2;
                    ldm_x2(bhf[nt], sBh + off);
                    ldm_x2(blf[nt], sBl + off);
                }
                #pragma unroll
                for (int mt = 0; mt < 4; mt++)
                    #pragma unroll
                    for (int nt = 0; nt < 4; nt++) {
                        float* c = acc[mt][nh*4 + nt];
                        mma16816(c, ahf[mt], bhf[nt]);
                        mma16816(c, ahf[mt], blf[nt]);
                        mma16816(c, alf[mt], bhf[nt]);
                    }
            }
        }
    }

    // ---------------- Epilogue ----------------
    const int rit = lane >> 2;
    const int cit = (lane & 3) * 2;

    #pragma unroll
    for (int mt = 0; mt < 4; mt++) {
        #pragma unroll
        for (int nt = 0; nt < 8; nt++) {
            int gc = n0 + wn*64 + nt*8 + cit;
            float* c = acc[mt][nt];
            if (bias) {
                float2 bb = *(const float2*)(bias + gc);
                c[0] += bb.x; c[1] += bb.y; c[2] += bb.x; c[3] += bb.y;
            }
            if (Rm) {
                int gr0 = m0 + wm*64 + mt*16 + rit;
                float2 r0 = *(const float2*)(Rm + (size_t)gr0 * N + gc);
                float2 r1 = *(const float2*)(Rm + (size_t)(gr0 + 8) * N + gc);
                c[0] += r0.x; c[1] += r0.y; c[2] += r1.x; c[3] += r1.y;
            }
            if (relu) {
                c[0] = fmaxf(c[0], 0.f); c[1] = fmaxf(c[1], 0.f);
                c[2] = fmaxf(c[2], 0.f); c[3] = fmaxf(c[3], 0.f);
            }
        }
    }

    if (lnG) {
        float2* red = (float2*)smem;
        __syncthreads();
        #pragma unroll
        for (int mt = 0; mt < 4; mt++) {
            float s0 = 0.f, q0 = 0.f, s1 = 0.f, q1 = 0.f;
            #pragma unroll
            for (int nt = 0; nt < 8; nt++) {
                float* c = acc[mt][nt];
                s0 += c[0] + c[1]; q0 += c[0]*c[0] + c[1]*c[1];
                s1 += c[2] + c[3]; q1 += c[2]*c[2] + c[3]*c[3];
            }
            #pragma unroll
            for (int o = 1; o < 4; o <<= 1) {
                s0 += __shfl_xor_sync(0xffffffffu, s0, o);
                q0 += __shfl_xor_sync(0xffffffffu, q0, o);
                s1 += __shfl_xor_sync(0xffffffffu, s1, o);
                q1 += __shfl_xor_sync(0xffffffffu, q1, o);
            }
            if ((lane & 3) == 0) {
                int r0 = wm*64 + mt*16 + rit;
                red[r0*4 + wn]       = make_float2(s0, q0);
                red[(r0 + 8)*4 + wn] = make_float2(s1, q1);
            }
        }
        __syncthreads();
        #pragma unroll
        for (int mt = 0; mt < 4; mt++) {
            int r0 = wm*64 + mt*16 + rit;
            float S0 = 0.f, Q0 = 0.f, S1 = 0.f, Q1 = 0.f;
            #pragma unroll
            for (int w = 0; w < 4; w++) {
                float2 p0 = red[r0*4 + w];
                float2 p1 = red[(r0 + 8)*4 + w];
                S0 += p0.x; Q0 += p0.y;
                S1 += p1.x; Q1 += p1.y;
            }
            float mu0 = S0 * (1.0f/256.0f);
            float mu1 = S1 * (1.0f/256.0f);
            float rs0 = rsqrtf(Q0 * (1.0f/256.0f) - mu0*mu0 + 1e-5f);
            float rs1 = rsqrtf(Q1 * (1.0f/256.0f) - mu1*mu1 + 1e-5f);
            #pragma unroll
            for (int nt = 0; nt < 8; nt++) {
                int gc = wn*64 + nt*8 + cit;
                float2 g2 = *(const float2*)(lnG + gc);
                float2 b2 = *(const float2*)(lnB + gc);
                float* c = acc[mt][nt];
                c[0] = (c[0] - mu0) * rs0 * g2.x + b2.x;
                c[1] = (c[1] - mu0) * rs0 * g2.y + b2.y;
                c[2] = (c[2] - mu1) * rs1 * g2.x + b2.x;
                c[3] = (c[3] - mu1) * rs1 * g2.y + b2.y;
            }
        }
    }

    #pragma unroll
    for (int mt = 0; mt < 4; mt++) {
        #pragma unroll
        for (int nt = 0; nt < 8; nt++) {
            int gr0 = m0 + wm*64 + mt*16 + rit;
            int gc  = n0 + wn*64 + nt*8 + cit;
            size_t o0 = (size_t)gr0 * N + gc;
            size_t o1 = (size_t)(gr0 + 8) * N + gc;
            float* c = acc[mt][nt];
            if (Cf) {
                *(float2*)(Cf + o0) = make_float2(c[0], c[1]);
                *(float2*)(Cf + o1) = make_float2(c[2], c[3]);
            }
            if (Ch) {
                __nv_bfloat16 h0, h1, h2, h3, l0, l1, l2, l3;
                split2(c[0], h0, l0); split2(c[1], h1, l1);
                split2(c[2], h2, l2); split2(c[3], h3, l3);
                *(__nv_bfloat162*)(Ch + o0) = __nv_bfloat162(h0, h1);
                *(__nv_bfloat162*)(Ch + o1) = __nv_bfloat162(h2, h3);
                *(__nv_bfloat162*)(Cl + o0) = __nv_bfloat162(l0, l1);
                *(__nv_bfloat162*)(Cl + o1) = __nv_bfloat162(l2, l3);
            }
            if (Cp) {
                *(__half2*)(Cp + o0) = __floats2half2_rn(c[0], c[1]);
                *(__half2*)(Cp + o1) = __floats2half2_rn(c[2], c[3]);
            }
        }
    }
}

// ==================================================================
// fp16x2 GEMM (FFN): C = A_fp16 @ (Bh+Bl)^T, 2 MMA terms.
// Same tile/pipeline/epilogue structure as bf16 kernel.
// ==================================================================
#define B_MATH (256*LDS*2)
#define STG_H (A_MAT + 2*B_MATH)       /* 51200 */
#define GEMMH_SMEM (STAGES*STG_H)      /* 153600 */

__device__ __forceinline__ void load_tiles_h(uint32_t st,
    const __half* a, const __half* bh, const __half* bl,
    int K, int k0, int tid)
{
    {
        int row = tid >> 1;
        int cb  = (tid & 1) * 32;
        uint32_t doff = (uint32_t)row * (LDS*2) + cb;
        const char* pa = (const char*)(a + (size_t)row * K + k0) + cb;
        CP_ASYNC16(st + doff,      pa);
        CP_ASYNC16(st + doff + 16, pa + 16);
    }
    {
        int row = tid;
        uint32_t doff = (uint32_t)row * (LDS*2);
        const char* pb = (const char*)(bh + (size_t)row * K + k0);
        const char* pc = (const char*)(bl + (size_t)row * K + k0);
        uint32_t b0 = st + A_MAT + doff;
        uint32_t b1 = st + A_MAT + B_MATH + doff;
        #pragma unroll
        for (int c = 0; c < 4; c++) {
            CP_ASYNC16(b0 + c*16, pb + c*16);
            CP_ASYNC16(b1 + c*16, pc + c*16);
        }
    }
}

__global__ __launch_bounds__(256, 1)
void gemm_fp16_kernel(int M, int N, int K,
    const __half* __restrict__ A,
    const __half* __restrict__ Bh, const __half* __restrict__ Bl,
    const float* __restrict__ bias, const float* __restrict__ Rm,
    const float* __restrict__ lnG, const float* __restrict__ lnB,
    float* __restrict__ Cf, __half* __restrict__ Cp, int relu)
{
    extern __shared__ char smem[];
    const uint32_t sbase = smem_u32(smem);
    const int tid  = threadIdx.x;
    const int wid  = tid >> 5;
    const int lane = tid & 31;
    const int wm = wid >> 2;
    const int wn = wid & 3;

    const int n0 = blockIdx.x * BN;
    const int m0 = blockIdx.y * BM;
    const __half* a  = A  + (size_t)m0 * K;
    const __half* bh = Bh + (size_t)n0 * K;
    const __half* bl = Bl + (size_t)n0 * K;

    const int NC = K / BK;

    float acc[4][8][4];
    #pragma unroll
    for (int mt = 0; mt < 4; mt++)
        #pragma unroll
        for (int nt = 0; nt < 8; nt++)
            #pragma unroll
            for (int j = 0; j < 4; j++) acc[mt][nt][j] = 0.f;

    #pragma unroll
    for (int s = 0; s < STAGES - 1; s++) {
        if (s < NC) load_tiles_h(sbase + s * STG_H, a, bh, bl, K, s * BK, tid);
        CP_COMMIT();
    }

    const int lr16 = lane & 15;
    const int lc16 = lane >> 4;
    const int lr8  = lr16 & 7;
    const int lc8  = lr16 >> 3;

    for (int i = 0; i < NC; i++) {
        asm volatile("cp.async.wait_group %0;" :: "n"(STAGES - 2));
        __syncthreads();

        int is = i + STAGES - 1;
        if (is < NC) load_tiles_h(sbase + (is % STAGES) * STG_H,
                                  a, bh, bl, K, is * BK, tid);
        CP_COMMIT();

        const uint32_t st  = sbase + (i % STAGES) * STG_H;
        const uint32_t sA  = st;
        const uint32_t sBh = st + A_MAT;
        const uint32_t sBl = st + A_MAT + B_MATH;

        #pragma unroll
        for (int ks = 0; ks < 2; ks++) {
            uint32_t af[4][4];
            #pragma unroll
            for (int mt = 0; mt < 4; mt++) {
                uint32_t off = ((uint32_t)(wm*64 + mt*16 + lr16) * LDS
                                + ks*16 + lc16*8) * 2;
                ldm_x4(af[mt], sA + off);
            }
            #pragma unroll
            for (int nh = 0; nh < 2; nh++) {
                uint32_t bhf[4][2], blf[4][2];
                #pragma unroll
                for (int nt = 0; nt < 4; nt++) {
                    uint32_t off = ((uint32_t)(wn*64 + nh*32 + nt*8 + lr8) * LDS
                                    + ks*16 + lc8*8) * 2;
                    ldm_x2(bhf[nt], sBh + off);
                    ldm_x2(blf[nt], sBl + off);
                }
                #pragma unroll
                for (int mt = 0; mt < 4; mt++)
                    #pragma unroll
                    for (int nt = 0; nt < 4; nt++) {
                        float* c = acc[mt][nh*4 + nt];
                        mma16816h(c, af[mt], bhf[nt]);
                        mma16816h(c, af[mt], blf[nt]);
                    }
            }
        }
    }

    // ---------------- Epilogue ----------------
    const int rit = lane >> 2;
    const int cit = (lane & 3) * 2;

    #pragma unroll
    for (int mt = 0; mt < 4; mt++) {
        #pragma unroll
        for (int nt = 0; nt < 8; nt++) {
            int gc = n0 + wn*64 + nt*8 + cit;
            float* c = acc[mt][nt];
            if (bias) {
                float2 bb = *(const float2*)(bias + gc);
                c[0] += bb.x; c[1] += bb.y; c[2] += bb.x; c[3] += bb.y;
            }
            if (Rm) {
                int gr0 = m0 + wm*64 + mt*16 + rit;
                float2 r0 = *(const float2*)(Rm + (size_t)gr0 * N + gc);
                float2 r1 = *(const float2*)(Rm + (size_t)(gr0 + 8) * N + gc);
                c[0] += r0.x; c[1] += r0.y; c[2] += r1.x; c[3] += r1.y;
            }
            if (relu) {
                c[0] = fmaxf(c[0], 0.f); c[1] = fmaxf(c[1], 0.f);
                c[2] = fmaxf(c[2], 0.f); c[3] = fmaxf(c[3], 0.f);
            }
        }
    }

    if (lnG) {
        float2* red = (float2*)smem;
        __syncthreads();
        #pragma unroll
        for (int mt = 0; mt < 4; mt++) {
            float s0 = 0.f, q0 = 0.f, s1 = 0.f, q1 = 0.f;
            #pragma unroll
            for (int nt = 0; nt < 8; nt++) {
                float* c = acc[mt][nt];
                s0 += c[0] + c[1]; q0 += c[0]*c[0] + c[1]*c[1];
                s1 += c[2] + c[3]; q1 += c[2]*c[2] + c[3]*c[3];
            }
            #pragma unroll
            for (int o = 1; o < 4; o <<= 1) {
                s0 += __shfl_xor_sync(0xffffffffu, s0, o);
                q0 += __shfl_xor_sync(0xffffffffu, q0, o);
                s1 += __shfl_xor_sync(0xffffffffu, s1, o);
                q1 += __shfl_xor_sync(0xffffffffu, q1, o);
            }
            if ((lane & 3) == 0) {
                int r0 = wm*64 + mt*16 + rit;
                red[r0*4 + wn]       = make_float2(s0, q0);
                red[(r0 + 8)*4 + wn] = make_float2(s1, q1);
            }
        }
        __syncthreads();
        #pragma unroll
        for (int mt = 0; mt < 4; mt++) {
            int r0 = wm*64 + mt*16 + rit;
            float S0 = 0.f, Q0 = 0.f, S1 = 0.f, Q1 = 0.f;
            #pragma unroll
            for (int w = 0; w < 4; w++) {
                float2 p0 = red[r0*4 + w];
                float2 p1 = red[(r0 + 8)*4 + w];
                S0 += p0.x; Q0 += p0.y;
                S1 += p1.x; Q1 += p1.y;
            }
            float mu0 = S0 * (1.0f/256.0f);
            float mu1 = S1 * (1.0f/256.0f);
            float rs0 = rsqrtf(Q0 * (1.0f/256.0f) - mu0*mu0 + 1e-5f);
            float rs1 = rsqrtf(Q1 * (1.0f/256.0f) - mu1*mu1 + 1e-5f);
            #pragma unroll
            for (int nt = 0; nt < 8; nt++) {
                int gc = wn*64 + nt*8 + cit;
                float2 g2 = *(const float2*)(lnG + gc);
                float2 b2 = *(const float2*)(lnB + gc);
                float* c = acc[mt][nt];
                c[0] = (c[0] - mu0) * rs0 * g2.x + b2.x;
                c[1] = (c[1] - mu0) * rs0 * g2.y + b2.y;
                c[2] = (c[2] - mu1) * rs1 * g2.x + b2.x;
                c[3] = (c[3] - mu1) * rs1 * g2.y + b2.y;
            }
        }
    }

    #pragma unroll
    for (int mt = 0; mt < 4; mt++) {
        #pragma unroll
        for (int nt = 0; nt < 8; nt++) {
            int gr0 = m0 + wm*64 + mt*16 + rit;
            int gc  = n0 + wn*64 + nt*8 + cit;
            size_t o0 = (size_t)gr0 * N + gc;
            size_t o1 = (size_t)(gr0 + 8) * N + gc;
            float* c = acc[mt][nt];
            if (Cf) {
                *(float2*)(Cf + o0) = make_float2(c[0], c[1]);
                *(float2*)(Cf + o1) = make_float2(c[2], c[3]);
            }
            if (Cp) {
                *(__half2*)(Cp + o0) = __floats2half2_rn(c[0], c[1]);
                *(__half2*)(Cp + o1) = __floats2half2_rn(c[2], c[3]);
            }
        }
    }
}

// ==================================================================
// Windowed attention — tensor-core FA2-style, 2 heads/block (R14)
// ==================================================================
#define HG 2
#define ALD2 72
#define SM_MAT (LWIN*ALD2)
#define ATTN_SMEM (6*SM_MAT*2)

__global__ __launch_bounds__(256)
void win_attn_kernel(const __nv_bfloat16* __restrict__ Qhp,
                     const __nv_bfloat16* __restrict__ Qlp, int qs,
                     const __nv_bfloat16* __restrict__ Khp,
                     const __nv_bfloat16* __restrict__ Klp,
                     const __nv_bfloat16* __restrict__ Vhp,
                     const __nv_bfloat16* __restrict__ Vlp, int kvs,
                     __nv_bfloat16* __restrict__ Oh, __nv_bfloat16* __restrict__ Ol,
                     int qH, int qW, int kH, int kW, int ks)
{
    extern __shared__ __nv_bfloat16 sm[];
    __nv_bfloat16 *SQh = sm,            *SQl = sm + SM_MAT,
                  *SKh = sm + 2*SM_MAT, *SKl = sm + 3*SM_MAT,
                  *SVh = sm + 4*SM_MAT, *SVl = sm + 5*SM_MAT;

    const int tid  = threadIdx.x;
    const int grp  = blockIdx.y;
    const int win  = blockIdx.x;
    const int nWw  = qW / WS;
    const int wpb  = (qH / WS) * nWw;
    const int n    = win / wpb;
    const int r    = win % wpb;
    const int wh   = r / nWw, ww = r % nWw;

    const size_t qbase = (size_t)n * qH * qW;
    const size_t kbase = (size_t)n * kH * kW;
    const int co = grp * (HG * DH);

    #pragma unroll
    for (int it = 0; it < 2; it++) {
        int idx = tid + it * 256;
        int row = idx >> 3;
        int c8  = (idx & 7) * 8;
        int i = row >> 3, j = row & 7;
        size_t qt = qbase + (size_t)(wh * WS + i) * qW + (ww * WS + j);
        int ki = (wh * ks + i) % kH;
        int kj = (ww * ks + j) % kW;
        size_t kt = kbase + (size_t)ki * kW + kj;

        *(uint4*)&SQh[row*ALD2 + c8] = *(const uint4*)(Qhp + qt * qs + co + c8);
        *(uint4*)&SQl[row*ALD2 + c8] = *(const uint4*)(Qlp + qt * qs + co + c8);
        *(uint4*)&SKh[row*ALD2 + c8] = *(const uint4*)(Khp + kt * kvs + co + c8);
        *(uint4*)&SKl[row*ALD2 + c8] = *(const uint4*)(Klp + kt * kvs + co + c8);
        *(uint4*)&SVh[row*ALD2 + c8] = *(const uint4*)(Vhp + kt * kvs + co + c8);
        *(uint4*)&SVl[row*ALD2 + c8] = *(const uint4*)(Vlp + kt * kvs + co + c8);
    }
    __syncthreads();

    const int wid  = tid >> 5;
    const int lane = tid & 31;
    const int hg   = wid >> 2;
    const int w4   = wid & 3;
    const int hb   = hg * DH;
    const int lr16 = lane & 15;
    const int lc16 = lane >> 4;
    const int lr8  = lr16 & 7;
    const int lc8  = lr16 >> 3;

    const uint32_t aQh = smem_u32(SQh), aQl = smem_u32(SQl);
    const uint32_t aKh = smem_u32(SKh), aKl = smem_u32(SKl);
    const uint32_t aVh = smem_u32(SVh), aVl = smem_u32(SVl);

    float sacc[8][4];
    #pragma unroll
    for (int nt = 0; nt < 8; nt++)
        #pragma unroll
        for (int j = 0; j < 4; j++) sacc[nt][j] = 0.f;

    #pragma unroll
    for (int k2 = 0; k2 < 2; k2++) {
        uint32_t qh[4], ql[4];
        uint32_t offA = ((uint32_t)(w4*16 + lr16) * ALD2 + hb + k2*16 + lc16*8) * 2;
        ldm_x4(qh, aQh + offA);
        ldm_x4(ql, aQl + offA);
        #pragma unroll
        for (int nt = 0; nt < 8; nt++) {
            uint32_t kh[2], kl[2];
            uint32_t offB = ((uint32_t)(nt*8 + lr8) * ALD2 + hb + k2*16 + lc8*8) * 2;
            ldm_x2(kh, aKh + offB);
            ldm_x2(kl, aKl + offB);
            mma16816(sacc[nt], qh, kh);
            mma16816(sacc[nt], qh, kl);
            mma16816(sacc[nt], ql, kh);
        }
    }

    const float SC = 0.17677669529663687f;
    float s0 = 0.f, s1 = 0.f;
    #pragma unroll
    for (int nt = 0; nt < 8; nt++) {
        sacc[nt][0] = __expf(sacc[nt][0] * SC);
        sacc[nt][1] = __expf(sacc[nt][1] * SC);
        sacc[nt][2] = __expf(sacc[nt][2] * SC);
        sacc[nt][3] = __expf(sacc[nt][3] * SC);
        s0 += sacc[nt][0] + sacc[nt][1];
        s1 += sacc[nt][2] + sacc[nt][3];
    }
    s0 += __shfl_xor_sync(0xffffffffu, s0, 1);
    s0 += __shfl_xor_sync(0xffffffffu, s0, 2);
    s1 += __shfl_xor_sync(0xffffffffu, s1, 1);
    s1 += __shfl_xor_sync(0xffffffffu, s1, 2);
    const float inv0 = 1.0f / s0;
    const float inv1 = 1.0f / s1;

    float oacc[4][4];
    #pragma unroll
    for (int nt = 0; nt < 4; nt++)
        #pragma unroll
        for (int j = 0; j < 4; j++) oacc[nt][j] = 0.f;

    #pragma unroll
    for (int kk = 0; kk < 4; kk++) {
        uint32_t ph[4], pl[4];
        #pragma unroll
        for (int h2 = 0; h2 < 2; h2++) {
            float* sp = sacc[kk*2 + h2];
            #pragma unroll
            for (int g = 0; g < 2; g++) {
                float p0 = sp[g*2], p1 = sp[g*2 + 1];
                __nv_bfloat16 hh0 = __float2bfloat16(p0);
                __nv_bfloat16 hh1 = __float2bfloat16(p1);
                ph[h2*2 + g] = bpack(hh0, hh1);
                pl[h2*2 + g] = bpack(
                    __float2bfloat16(p0 - __bfloat162float(hh0)),
                    __float2bfloat16(p1 - __bfloat162float(hh1)));
            }
        }
        #pragma unroll
        for (int nt = 0; nt < 4; nt++) {
            uint32_t vh[2], vl[2];
            uint32_t offV = ((uint32_t)(kk*16 + lr16) * ALD2 + hb + nt*8) * 2;
            ldm_x2_trans(vh, aVh + offV);
            ldm_x2_trans(vl, aVl + offV);
            mma16816(oacc[nt], ph, vh);
            mma16816(oacc[nt], ph, vl);
            mma16816(oacc[nt], pl, vh);
        }
    }

    const int cit = (lane & 3) * 2;
    const int oc  = co + hb;
    int r0 = w4*16 + (lane >> 2);
    int r1 = r0 + 8;
    int i0 = r0 >> 3, j0 = r0 & 7;
    int i1 = r1 >> 3, j1 = r1 & 7;
    size_t t0 = qbase + (size_t)(wh * WS + i0) * qW + (ww * WS + j0);
    size_t t1 = qbase + (size_t)(wh * WS + i1) * qW + (ww * WS + j1);
    size_t ob0 = t0 * C_DIM + oc + cit;
    size_t ob1 = t1 * C_DIM + oc + cit;

    #pragma unroll
    for (int nt = 0; nt < 4; nt++) {
        float v0 = oacc[nt][0] * inv0;
        float v1 = oacc[nt][1] * inv0;
        float v2 = oacc[nt][2] * inv1;
        float v3 = oacc[nt][3] * inv1;
        __nv_bfloat16 h0, h1, h2, h3, l0, l1, l2, l3;
        split2(v0, h0, l0); split2(v1, h1, l1);
        split2(v2, h2, l2); split2(v3, h3, l3);
        *(__nv_bfloat162*)(Oh + ob0 + nt*8) = __nv_bfloat162(h0, h1);
        *(__nv_bfloat162*)(Ol + ob0 + nt*8) = __nv_bfloat162(l0, l1);
        *(__nv_bfloat162*)(Oh + ob1 + nt*8) = __nv_bfloat162(h2, h3);
        *(__nv_bfloat162*)(Ol + ob1 + nt*8) = __nv_bfloat162(l2, l3);
    }
}

// ==================================================================
// 4x4 average pool (NHWC), fp32 + bf16 hi/lo out
// ==================================================================
__global__ __launch_bounds__(256)
void avgpool_kernel(const float* __restrict__ in, float* __restrict__ outf,
                    __nv_bfloat16* __restrict__ outh, __nv_bfloat16* __restrict__ outl)
{
    int t = blockIdx.x;
    int c = threadIdx.x;
    int n = t / (H1 * W1);
    int r = t % (H1 * W1);
    int oh = r / W1, ow = r % W1;
    float s = 0.f;
    #pragma unroll
    for (int dy = 0; dy < 4; dy++)
        #pragma unroll
        for (int dx = 0; dx < 4; dx++) {
            size_t tok = (size_t)n * H0 * W0 + (size_t)(oh * 4 + dy) * W0 + (ow * 4 + dx);
            s += in[tok * C_DIM + c];
        }
    s *= (1.0f / 16.0f);
    size_t o = (size_t)t * C_DIM + c;
    outf[o] = s;
    __nv_bfloat16 h, l;
    split2(s, h, l);
    outh[o] = h;
    outl[o] = l;
}

// ==================================================================
// Host side
// ==================================================================
#define WT_QKV  0
#define WT_SAF  196608
#define WT_CAQ  262144
#define WT_CAKV 327680
#define WT_CAF  458752
#define WP_W1   0
#define WP_W2   262144

extern "C" void kernel_launch(void* const* d_in, const int* in_sizes, int n_in,
                              void* d_out, int out_size)
{
    const float* x       = (const float*)d_in[0];
    const float* sa_wq   = (const float*)d_in[1];
    const float* sa_wk   = (const float*)d_in[2];
    const float* sa_wv   = (const float*)d_in[3];
    const float* sa_wf   = (const float*)d_in[4];
    const float* sa_bf   = (const float*)d_in[5];
    const float* ca_wq   = (const float*)d_in[6];
    const float* ca_wk   = (const float*)d_in[7];
    const float* ca_wv   = (const float*)d_in[8];
    const float* ca_wf   = (const float*)d_in[9];
    const float* ca_bf   = (const float*)d_in[10];
    const float* ln_self_g = (const float*)d_in[11];
    const float* ln_self_b = (const float*)d_in[12];
    const float* ln_cross_g= (const float*)d_in[13];
    const float* ln_cross_b= (const float*)d_in[14];
    const float* ffn_w1  = (const float*)d_in[15];
    const float* ffn_b1  = (const float*)d_in[16];
    const float* ffn_w2  = (const float*)d_in[17];
    const float* ffn_b2  = (const float*)d_in[18];
    const float* ln_out_g= (const float*)d_in[19];
    const float* ln_out_b= (const float*)d_in[20];
    float* out = (float*)d_out;

    float *bufA, *bufB, *bufL0;
    __nv_bfloat16 *qkvh, *qkvl, *ash, *asl, *l0h, *l0l, *fh, *fl, *wth, *wtl;
    __half *wph, *wpl;
    cudaGetSymbolAddress((void**)&bufA,  g_bufA);
    cudaGetSymbolAddress((void**)&bufB,  g_bufB);
    cudaGetSymbolAddress((void**)&bufL0, g_bufL0);
    cudaGetSymbolAddress((void**)&qkvh,  g_qkvh);
    cudaGetSymbolAddress((void**)&qkvl,  g_qkvl);
    cudaGetSymbolAddress((void**)&ash,   g_ash);
    cudaGetSymbolAddress((void**)&asl,   g_asl);
    cudaGetSymbolAddress((void**)&l0h,   g_l0h);
    cudaGetSymbolAddress((void**)&l0l,   g_l0l);
    cudaGetSymbolAddress((void**)&fh,    g_fh);
    cudaGetSymbolAddress((void**)&fl,    g_fl);
    cudaGetSymbolAddress((void**)&wth,   g_wth);
    cudaGetSymbolAddress((void**)&wtl,   g_wtl);
    cudaGetSymbolAddress((void**)&wph,   g_wph);
    cudaGetSymbolAddress((void**)&wpl,   g_wpl);

    __half* act16 = (__half*)ash;   /* fp16 FFN1 input (aliases ash rows) */
    __half* f16   = (__half*)fh;    /* fp16 FFN1 output */

    cudaFuncSetAttribute(gemm_tc_kernel,
                         cudaFuncAttributeMaxDynamicSharedMemorySize, GEMM_SMEM);
    cudaFuncSetAttribute(gemm_fp16_kernel,
                         cudaFuncAttributeMaxDynamicSharedMemorySize, GEMMH_SMEM);
    cudaFuncSetAttribute(win_attn_kernel,
                         cudaFuncAttributeMaxDynamicSharedMemorySize, ATTN_SMEM);

    dim3 tb(32, 8);

    auto gemm = [&](int M, int N, int K,
                    const __nv_bfloat16* Ahp, const __nv_bfloat16* Alp,
                    const __nv_bfloat16* Bhp, const __nv_bfloat16* Blp,
                    const float* bias, const float* resid,
                    const float* lnG, const float* lnB,
                    float* Cf, __nv_bfloat16* Ch, __nv_bfloat16* Cl,
                    __half* Cp, int relu) {
        dim3 grid(N / BN, M / BM);
        gemm_tc_kernel<<<grid, 256, GEMM_SMEM>>>(M, N, K, Ahp, Alp, Bhp, Blp,
                                                 bias, resid, lnG, lnB,
                                                 Cf, Ch, Cl, Cp, relu);
    };

    // --- batched weight prep ---
    {
        WPrepArgs a;
        const float* srcs[8] = {sa_wq, sa_wk, sa_wv, sa_wf, ca_wq,
                                ca_wk, ca_wv, ca_wf};
        int Ks[8]  = {256,256,256,256,256,256,256,256};
        int Ns[8]  = {256,256,256,256,256,256,256,256};
        int offs[8] = {WT_QKV, WT_QKV + 65536, WT_QKV + 131072, WT_SAF,
                       WT_CAQ, WT_CAKV, WT_CAKV + 65536, WT_CAF};
        for (int j = 0; j < 8; j++) {
            a.src[j] = srcs[j]; a.K[j] = Ks[j]; a.N[j] = Ns[j]; a.off[j] = offs[j];
        }
        wprep_kernel<<<dim3(8, 8, 8), tb>>>(a, wth, wtl);
        wprep_h_kernel<<<dim3(32, 32, 2), tb>>>(ffn_w1, ffn_w2, wph, wpl);
    }

    // 0. NCHW -> NHWC (+split)
    transpose_split_kernel<<<dim3(H0*W0/32, C_DIM/32, NB), tb>>>(x, bufA, ash, asl,
                                                                 C_DIM, H0*W0);

    // 1. Self-attention level 0
    gemm(T0, 768, 256, ash, asl, wth + WT_QKV, wtl + WT_QKV,
         nullptr, nullptr, nullptr, nullptr, nullptr, qkvh, qkvl, nullptr, 0);
    win_attn_kernel<<<dim3(NB*16*16, NHEADS/HG), 256, ATTN_SMEM>>>(
        qkvh, qkvl, 768, qkvh + 256, qkvl + 256, qkvh + 512, qkvl + 512, 768,
        ash, asl, H0, W0, H0, W0, WS);
    gemm(T0, 256, 256, ash, asl, wth + WT_SAF, wtl + WT_SAF,
         sa_bf, bufA, ln_self_g, ln_self_b, bufL0, l0h, l0l, nullptr, 0);

    // 2. avgpool
    avgpool_kernel<<<T1, 256>>>(bufL0, bufB, ash, asl);

    // 3. Self-attention level 1
    gemm(T1, 768, 256, ash, asl, wth + WT_QKV, wtl + WT_QKV,
         nullptr, nullptr, nullptr, nullptr, nullptr, qkvh, qkvl, nullptr, 0);
    win_attn_kernel<<<dim3(NB*4*4, NHEADS/HG), 256, ATTN_SMEM>>>(
        qkvh, qkvl, 768, qkvh + 256, qkvl + 256, qkvh + 512, qkvl + 512, 768,
        ash, asl, H1, W1, H1, W1, WS);
    gemm(T1, 256, 256, ash, asl, wth + WT_SAF, wtl + WT_SAF,
         sa_bf, bufB, ln_self_g, ln_self_b, nullptr, ash, asl, nullptr, 0);

    // 4. Cross-attention
    gemm(T1, 512, 256, ash, asl, wth + WT_CAKV, wtl + WT_CAKV,
         nullptr, nullptr, nullptr, nullptr, nullptr, qkvh, qkvl, nullptr, 0);
    gemm(T0, 256, 256, l0h, l0l, wth + WT_CAQ, wtl + WT_CAQ,
         nullptr, nullptr, nullptr, nullptr, nullptr, fh, fl, nullptr, 0);
    win_attn_kernel<<<dim3(NB*16*16, NHEADS/HG), 256, ATTN_SMEM>>>(
        fh, fl, 256, qkvh, qkvl, qkvh + 256, qkvl + 256, 512,
        ash, asl, H0, W0, H1, W1, 2);
    // CAF: fp32 out (FFN2 residual) + fused cross-LN + fp16 act for FFN1
    gemm(T0, 256, 256, ash, asl, wth + WT_CAF, wtl + WT_CAF,
         ca_bf, bufL0, ln_cross_g, ln_cross_b, bufB, nullptr, nullptr, act16, 0);

    // 5. FFN in fp16x2 (+fused final LN on FFN2)
    {
        dim3 g1(DF_DIM / BN, T0 / BM);
        gemm_fp16_kernel<<<g1, 256, GEMMH_SMEM>>>(T0, DF_DIM, 256,
            act16, wph + WP_W1, wpl + WP_W1,
            ffn_b1, nullptr, nullptr, nullptr, nullptr, f16, 1);
        dim3 g2(C_DIM / BN, T0 / BM);
        gemm_fp16_kernel<<<g2, 256, GEMMH_SMEM>>>(T0, C_DIM, DF_DIM,
            f16, wph + WP_W2, wpl + WP_W2,
            ffn_b2, bufB, ln_out_g, ln_out_b, bufL0, nullptr, 0);
    }

    // 6. NHWC -> NCHW
    transpose_split_kernel<<<dim3(C_DIM/32, H0*W0/32, NB), tb>>>(bufL0, out,
        nullptr, nullptr, H0*W0, C_DIM);
}

// round 17
// speedup vs baseline: 1.3308x; 1.1347x over previous
#include <cuda_runtime.h>
#include <cuda_bf16.h>
#include <cuda_fp16.h>
#include <cstdint>

#define C_DIM 256
#define DF_DIM 1024
#define NB 8
#define H0 128
#define W0 128
#define T0 (NB*H0*W0)      /* 131072 */
#define H1 32
#define W1 32
#define T1 (NB*H1*W1)      /* 8192 */
#define NHEADS 8
#define DH 32
#define WS 8
#define LWIN 64

// ==================================================================
// Scratch (device globals — allocation-free)
// ==================================================================
__device__ float g_bufA  [(size_t)T0*C_DIM];
__device__ float g_bufB  [(size_t)T0*C_DIM];
__device__ float g_bufL0 [(size_t)T0*C_DIM];
__device__ __nv_bfloat16 g_qkvh[(size_t)T0*768];
__device__ __nv_bfloat16 g_qkvl[(size_t)T0*768];
__device__ __nv_bfloat16 g_ash[(size_t)T0*DF_DIM];   /* aliased as __half actA */
__device__ __nv_bfloat16 g_asl[(size_t)T0*DF_DIM];   /* aliased as __half actB */
__device__ __nv_bfloat16 g_fh [(size_t)T0*DF_DIM];   /* bf16 cross-Q hi / fp16 FFN mid */
__device__ __nv_bfloat16 g_fl [(size_t)T0*DF_DIM];
__device__ __half g_wph[1048576];
__device__ __half g_wpl[1048576];

// ==================================================================
// PTX helpers
// ==================================================================
__device__ __forceinline__ uint32_t smem_u32(const void* p) {
    uint32_t a;
    asm("{ .reg .u64 t; cvta.to.shared.u64 t, %1; cvt.u32.u64 %0, t; }"
        : "=r"(a) : "l"(p));
    return a;
}

#define CP_ASYNC16(dst, src) \
    asm volatile("cp.async.cg.shared.global [%0], [%1], 16;" :: "r"(dst), "l"(src) : "memory")
#define CP_COMMIT() asm volatile("cp.async.commit_group;" ::: "memory")

__device__ __forceinline__ void ldm_x4(uint32_t* r, uint32_t addr) {
    asm volatile("ldmatrix.sync.aligned.m8n8.x4.shared.b16 {%0,%1,%2,%3}, [%4];"
        : "=r"(r[0]), "=r"(r[1]), "=r"(r[2]), "=r"(r[3]) : "r"(addr));
}
__device__ __forceinline__ void ldm_x2(uint32_t* r, uint32_t addr) {
    asm volatile("ldmatrix.sync.aligned.m8n8.x2.shared.b16 {%0,%1}, [%2];"
        : "=r"(r[0]), "=r"(r[1]) : "r"(addr));
}
__device__ __forceinline__ void ldm_x2_trans(uint32_t* r, uint32_t addr) {
    asm volatile("ldmatrix.sync.aligned.m8n8.x2.trans.shared.b16 {%0,%1}, [%2];"
        : "=r"(r[0]), "=r"(r[1]) : "r"(addr));
}
__device__ __forceinline__ void mma16816(float* c, const uint32_t* a, const uint32_t* b) {
    asm volatile("mma.sync.aligned.m16n8k16.row.col.f32.bf16.bf16.f32 "
        "{%0,%1,%2,%3}, {%4,%5,%6,%7}, {%8,%9}, {%0,%1,%2,%3};"
        : "+f"(c[0]), "+f"(c[1]), "+f"(c[2]), "+f"(c[3])
        : "r"(a[0]), "r"(a[1]), "r"(a[2]), "r"(a[3]), "r"(b[0]), "r"(b[1]));
}
__device__ __forceinline__ void mma16816h(float* c, const uint32_t* a, const uint32_t* b) {
    asm volatile("mma.sync.aligned.m16n8k16.row.col.f32.f16.f16.f32 "
        "{%0,%1,%2,%3}, {%4,%5,%6,%7}, {%8,%9}, {%0,%1,%2,%3};"
        : "+f"(c[0]), "+f"(c[1]), "+f"(c[2]), "+f"(c[3])
        : "r"(a[0]), "r"(a[1]), "r"(a[2]), "r"(a[3]), "r"(b[0]), "r"(b[1]));
}

__device__ __forceinline__ void split2(float v, __nv_bfloat16& h, __nv_bfloat16& l) {
    h = __float2bfloat16(v);
    l = __float2bfloat16(v - __bfloat162float(h));
}
__device__ __forceinline__ uint32_t bpack(__nv_bfloat16 a, __nv_bfloat16 b) {
    __nv_bfloat162 t(a, b);
    return *reinterpret_cast<uint32_t*>(&t);
}

// ==================================================================
// Transpose per-batch [P][Q] -> [Q][P], optional fused fp16 out
// ==================================================================
__global__ void transpose_split_kernel(const float* __restrict__ in,
                                       float* __restrict__ out,
                                       __half* __restrict__ h16,
                                       int P, int Q)
{
    __shared__ float tile[32][33];
    const size_t bofs = (size_t)blockIdx.z * P * Q;
    in += bofs;
    int p0 = blockIdx.y * 32;
    int q0 = blockIdx.x * 32;
    int tx = threadIdx.x, ty = threadIdx.y;
    #pragma unroll
    for (int i = ty; i < 32; i += 8)
        tile[i][tx] = in[(size_t)(p0 + i) * Q + q0 + tx];
    __syncthreads();
    #pragma unroll
    for (int i = ty; i < 32; i += 8) {
        float v = tile[tx][i];
        size_t o = bofs + (size_t)(q0 + i) * P + p0 + tx;
        out[o] = v;
        if (h16) h16[o] = __float2half(v);
    }
}

// ==================================================================
// Batched fp16 weight prep: 10 matrices, transpose+split, one launch
// ==================================================================
struct WPrepArgs {
    const float* src[10];
    int K[10];
    int N[10];
    int off[10];
};

__global__ void wprep_h_kernel(WPrepArgs a,
                               __half* __restrict__ hi_base,
                               __half* __restrict__ lo_base)
{
    __shared__ float tile[32][33];
    const int j = blockIdx.z;
    const int K = a.K[j], N = a.N[j];
    const int n0 = blockIdx.x * 32;
    const int k0 = blockIdx.y * 32;
    if (n0 >= N || k0 >= K) return;
    const float* W = a.src[j];
    __half* hi = hi_base + a.off[j];
    __half* lo = lo_base + a.off[j];
    int tx = threadIdx.x, ty = threadIdx.y;
    #pragma unroll
    for (int i = ty; i < 32; i += 8)
        tile[i][tx] = W[(size_t)(k0 + i) * N + n0 + tx];
    __syncthreads();
    #pragma unroll
    for (int i = ty; i < 32; i += 8) {
        float v = tile[tx][i];
        __half h = __float2half(v);
        __half l = __float2half(v - __half2float(h));
        size_t o = (size_t)(n0 + i) * K + k0 + tx;
        hi[o] = h;
        lo[o] = l;
    }
}

// ==================================================================
// fp16x2 GEMM: C[M,N] = A_fp16[M,K] @ (Bh+Bl)[N,K]^T, 2 MMA terms.
// CTA 128x256, warp tile 64x64, BK=32, 3-stage cp.async.
// Epilogues: bias / residual / relu / LayerNorm (N==256) /
// outputs: fp32 Cf, bf16 hi/lo Ch+Cl, fp16 Cp.
// ==================================================================
#define BM 128
#define BN 256
#define BK 32
#define LDS 40
#define A_MAT (128*LDS*2)
#define B_MATH (256*LDS*2)
#define STG_H (A_MAT + 2*B_MATH)
#define STAGES 3
#define GEMMH_SMEM (STAGES*STG_H)

__device__ __forceinline__ void load_tiles_h(uint32_t st,
    const __half* a, const __half* bh, const __half* bl,
    int K, int k0, int tid)
{
    {
        int row = tid >> 1;
        int cb  = (tid & 1) * 32;
        uint32_t doff = (uint32_t)row * (LDS*2) + cb;
        const char* pa = (const char*)(a + (size_t)row * K + k0) + cb;
        CP_ASYNC16(st + doff,      pa);
        CP_ASYNC16(st + doff + 16, pa + 16);
    }
    {
        int row = tid;
        uint32_t doff = (uint32_t)row * (LDS*2);
        const char* pb = (const char*)(bh + (size_t)row * K + k0);
        const char* pc = (const char*)(bl + (size_t)row * K + k0);
        uint32_t b0 = st + A_MAT + doff;
        uint32_t b1 = st + A_MAT + B_MATH + doff;
        #pragma unroll
        for (int c = 0; c < 4; c++) {
            CP_ASYNC16(b0 + c*16, pb + c*16);
            CP_ASYNC16(b1 + c*16, pc + c*16);
        }
    }
}

__global__ __launch_bounds__(256, 1)
void gemm_fp16_kernel(int M, int N, int K,
    const __half* __restrict__ A,
    const __half* __restrict__ Bh, const __half* __restrict__ Bl,
    const float* __restrict__ bias, const float* __restrict__ Rm,
    const float* __restrict__ lnG, const float* __restrict__ lnB,
    float* __restrict__ Cf,
    __nv_bfloat16* __restrict__ Ch, __nv_bfloat16* __restrict__ Cl,
    __half* __restrict__ Cp, int relu)
{
    extern __shared__ char smem[];
    const uint32_t sbase = smem_u32(smem);
    const int tid  = threadIdx.x;
    const int wid  = tid >> 5;
    const int lane = tid & 31;
    const int wm = wid >> 2;
    const int wn = wid & 3;

    const int n0 = blockIdx.x * BN;
    const int m0 = blockIdx.y * BM;
    const __half* a  = A  + (size_t)m0 * K;
    const __half* bh = Bh + (size_t)n0 * K;
    const __half* bl = Bl + (size_t)n0 * K;

    const int NC = K / BK;

    float acc[4][8][4];
    #pragma unroll
    for (int mt = 0; mt < 4; mt++)
        #pragma unroll
        for (int nt = 0; nt < 8; nt++)
            #pragma unroll
            for (int j = 0; j < 4; j++) acc[mt][nt][j] = 0.f;

    #pragma unroll
    for (int s = 0; s < STAGES - 1; s++) {
        if (s < NC) load_tiles_h(sbase + s * STG_H, a, bh, bl, K, s * BK, tid);
        CP_COMMIT();
    }

    const int lr16 = lane & 15;
    const int lc16 = lane >> 4;
    const int lr8  = lr16 & 7;
    const int lc8  = lr16 >> 3;

    for (int i = 0; i < NC; i++) {
        asm volatile("cp.async.wait_group %0;" :: "n"(STAGES - 2));
        __syncthreads();

        int is = i + STAGES - 1;
        if (is < NC) load_tiles_h(sbase + (is % STAGES) * STG_H,
                                  a, bh, bl, K, is * BK, tid);
        CP_COMMIT();

        const uint32_t st  = sbase + (i % STAGES) * STG_H;
        const uint32_t sA  = st;
        const uint32_t sBh = st + A_MAT;
        const uint32_t sBl = st + A_MAT + B_MATH;

        #pragma unroll
        for (int ks = 0; ks < 2; ks++) {
            uint32_t af[4][4];
            #pragma unroll
            for (int mt = 0; mt < 4; mt++) {
                uint32_t off = ((uint32_t)(wm*64 + mt*16 + lr16) * LDS
                                + ks*16 + lc16*8) * 2;
                ldm_x4(af[mt], sA + off);
            }
            #pragma unroll
            for (int nh = 0; nh < 2; nh++) {
                uint32_t bhf[4][2], blf[4][2];
                #pragma unroll
                for (int nt = 0; nt < 4; nt++) {
                    uint32_t off = ((uint32_t)(wn*64 + nh*32 + nt*8 + lr8) * LDS
                                    + ks*16 + lc8*8) * 2;
                    ldm_x2(bhf[nt], sBh + off);
                    ldm_x2(blf[nt], sBl + off);
                }
                #pragma unroll
                for (int mt = 0; mt < 4; mt++)
                    #pragma unroll
                    for (int nt = 0; nt < 4; nt++) {
                        float* c = acc[mt][nh*4 + nt];
                        mma16816h(c, af[mt], bhf[nt]);
                        mma16816h(c, af[mt], blf[nt]);
                    }
            }
        }
    }

    // ---------------- Epilogue ----------------
    const int rit = lane >> 2;
    const int cit = (lane & 3) * 2;

    #pragma unroll
    for (int mt = 0; mt < 4; mt++) {
        #pragma unroll
        for (int nt = 0; nt < 8; nt++) {
            int gc = n0 + wn*64 + nt*8 + cit;
            float* c = acc[mt][nt];
            if (bias) {
                float2 bb = *(const float2*)(bias + gc);
                c[0] += bb.x; c[1] += bb.y; c[2] += bb.x; c[3] += bb.y;
            }
            if (Rm) {
                int gr0 = m0 + wm*64 + mt*16 + rit;
                float2 r0 = *(const float2*)(Rm + (size_t)gr0 * N + gc);
                float2 r1 = *(const float2*)(Rm + (size_t)(gr0 + 8) * N + gc);
                c[0] += r0.x; c[1] += r0.y; c[2] += r1.x; c[3] += r1.y;
            }
            if (relu) {
                c[0] = fmaxf(c[0], 0.f); c[1] = fmaxf(c[1], 0.f);
                c[2] = fmaxf(c[2], 0.f); c[3] = fmaxf(c[3], 0.f);
            }
        }
    }

    if (lnG) {
        float2* red = (float2*)smem;
        __syncthreads();
        #pragma unroll
        for (int mt = 0; mt < 4; mt++) {
            float s0 = 0.f, q0 = 0.f, s1 = 0.f, q1 = 0.f;
            #pragma unroll
            for (int nt = 0; nt < 8; nt++) {
                float* c = acc[mt][nt];
                s0 += c[0] + c[1]; q0 += c[0]*c[0] + c[1]*c[1];
                s1 += c[2] + c[3]; q1 += c[2]*c[2] + c[3]*c[3];
            }
            #pragma unroll
            for (int o = 1; o < 4; o <<= 1) {
                s0 += __shfl_xor_sync(0xffffffffu, s0, o);
                q0 += __shfl_xor_sync(0xffffffffu, q0, o);
                s1 += __shfl_xor_sync(0xffffffffu, s1, o);
                q1 += __shfl_xor_sync(0xffffffffu, q1, o);
            }
            if ((lane & 3) == 0) {
                int r0 = wm*64 + mt*16 + rit;
                red[r0*4 + wn]       = make_float2(s0, q0);
                red[(r0 + 8)*4 + wn] = make_float2(s1, q1);
            }
        }
        __syncthreads();
        #pragma unroll
        for (int mt = 0; mt < 4; mt++) {
            int r0 = wm*64 + mt*16 + rit;
            float S0 = 0.f, Q0 = 0.f, S1 = 0.f, Q1 = 0.f;
            #pragma unroll
            for (int w = 0; w < 4; w++) {
                float2 p0 = red[r0*4 + w];
                float2 p1 = red[(r0 + 8)*4 + w];
                S0 += p0.x; Q0 += p0.y;
                S1 += p1.x; Q1 += p1.y;
            }
            float mu0 = S0 * (1.0f/256.0f);
            float mu1 = S1 * (1.0f/256.0f);
            float rs0 = rsqrtf(Q0 * (1.0f/256.0f) - mu0*mu0 + 1e-5f);
            float rs1 = rsqrtf(Q1 * (1.0f/256.0f) - mu1*mu1 + 1e-5f);
            #pragma unroll
            for (int nt = 0; nt < 8; nt++) {
                int gc = wn*64 + nt*8 + cit;
                float2 g2 = *(const float2*)(lnG + gc);
                float2 b2 = *(const float2*)(lnB + gc);
                float* c = acc[mt][nt];
                c[0] = (c[0] - mu0) * rs0 * g2.x + b2.x;
                c[1] = (c[1] - mu0) * rs0 * g2.y + b2.y;
                c[2] = (c[2] - mu1) * rs1 * g2.x + b2.x;
                c[3] = (c[3] - mu1) * rs1 * g2.y + b2.y;
            }
        }
    }

    #pragma unroll
    for (int mt = 0; mt < 4; mt++) {
        #pragma unroll
        for (int nt = 0; nt < 8; nt++) {
            int gr0 = m0 + wm*64 + mt*16 + rit;
            int gc  = n0 + wn*64 + nt*8 + cit;
            size_t o0 = (size_t)gr0 * N + gc;
            size_t o1 = (size_t)(gr0 + 8) * N + gc;
            float* c = acc[mt][nt];
            if (Cf) {
                *(float2*)(Cf + o0) = make_float2(c[0], c[1]);
                *(float2*)(Cf + o1) = make_float2(c[2], c[3]);
            }
            if (Ch) {
                __nv_bfloat16 h0, h1, h2, h3, l0, l1, l2, l3;
                split2(c[0], h0, l0); split2(c[1], h1, l1);
                split2(c[2], h2, l2); split2(c[3], h3, l3);
                *(__nv_bfloat162*)(Ch + o0) = __nv_bfloat162(h0, h1);
                *(__nv_bfloat162*)(Ch + o1) = __nv_bfloat162(h2, h3);
                *(__nv_bfloat162*)(Cl + o0) = __nv_bfloat162(l0, l1);
                *(__nv_bfloat162*)(Cl + o1) = __nv_bfloat162(l2, l3);
            }
            if (Cp) {
                *(__half2*)(Cp + o0) = __floats2half2_rn(c[0], c[1]);
                *(__half2*)(Cp + o1) = __floats2half2_rn(c[2], c[3]);
            }
        }
    }
}

// ==================================================================
// Windowed attention — tensor-core FA2-style, 2 heads/block.
// bf16x3 internal math (Q/K/V bf16 hi/lo in); single fp16 out.
// ==================================================================
#define HG 2
#define ALD2 72
#define SM_MAT (LWIN*ALD2)
#define ATTN_SMEM (6*SM_MAT*2)

__global__ __launch_bounds__(256)
void win_attn_kernel(const __nv_bfloat16* __restrict__ Qhp,
                     const __nv_bfloat16* __restrict__ Qlp, int qs,
                     const __nv_bfloat16* __restrict__ Khp,
                     const __nv_bfloat16* __restrict__ Klp,
                     const __nv_bfloat16* __restrict__ Vhp,
                     const __nv_bfloat16* __restrict__ Vlp, int kvs,
                     __half* __restrict__ O,
                     int qH, int qW, int kH, int kW, int ks)
{
    extern __shared__ __nv_bfloat16 sm[];
    __nv_bfloat16 *SQh = sm,            *SQl = sm + SM_MAT,
                  *SKh = sm + 2*SM_MAT, *SKl = sm + 3*SM_MAT,
                  *SVh = sm + 4*SM_MAT, *SVl = sm + 5*SM_MAT;

    const int tid  = threadIdx.x;
    const int grp  = blockIdx.y;
    const int win  = blockIdx.x;
    const int nWw  = qW / WS;
    const int wpb  = (qH / WS) * nWw;
    const int n    = win / wpb;
    const int r    = win % wpb;
    const int wh   = r / nWw, ww = r % nWw;

    const size_t qbase = (size_t)n * qH * qW;
    const size_t kbase = (size_t)n * kH * kW;
    const int co = grp * (HG * DH);

    #pragma unroll
    for (int it = 0; it < 2; it++) {
        int idx = tid + it * 256;
        int row = idx >> 3;
        int c8  = (idx & 7) * 8;
        int i = row >> 3, j = row & 7;
        size_t qt = qbase + (size_t)(wh * WS + i) * qW + (ww * WS + j);
        int ki = (wh * ks + i) % kH;
        int kj = (ww * ks + j) % kW;
        size_t kt = kbase + (size_t)ki * kW + kj;

        *(uint4*)&SQh[row*ALD2 + c8] = *(const uint4*)(Qhp + qt * qs + co + c8);
        *(uint4*)&SQl[row*ALD2 + c8] = *(const uint4*)(Qlp + qt * qs + co + c8);
        *(uint4*)&SKh[row*ALD2 + c8] = *(const uint4*)(Khp + kt * kvs + co + c8);
        *(uint4*)&SKl[row*ALD2 + c8] = *(const uint4*)(Klp + kt * kvs + co + c8);
        *(uint4*)&SVh[row*ALD2 + c8] = *(const uint4*)(Vhp + kt * kvs + co + c8);
        *(uint4*)&SVl[row*ALD2 + c8] = *(const uint4*)(Vlp + kt * kvs + co + c8);
    }
    __syncthreads();

    const int wid  = tid >> 5;
    const int lane = tid & 31;
    const int hg   = wid >> 2;
    const int w4   = wid & 3;
    const int hb   = hg * DH;
    const int lr16 = lane & 15;
    const int lc16 = lane >> 4;
    const int lr8  = lr16 & 7;
    const int lc8  = lr16 >> 3;

    const uint32_t aQh = smem_u32(SQh), aQl = smem_u32(SQl);
    const uint32_t aKh = smem_u32(SKh), aKl = smem_u32(SKl);
    const uint32_t aVh = smem_u32(SVh), aVl = smem_u32(SVl);

    float sacc[8][4];
    #pragma unroll
    for (int nt = 0; nt < 8; nt++)
        #pragma unroll
        for (int j = 0; j < 4; j++) sacc[nt][j] = 0.f;

    #pragma unroll
    for (int k2 = 0; k2 < 2; k2++) {
        uint32_t qh[4], ql[4];
        uint32_t offA = ((uint32_t)(w4*16 + lr16) * ALD2 + hb + k2*16 + lc16*8) * 2;
        ldm_x4(qh, aQh + offA);
        ldm_x4(ql, aQl + offA);
        #pragma unroll
        for (int nt = 0; nt < 8; nt++) {
            uint32_t kh[2], kl[2];
            uint32_t offB = ((uint32_t)(nt*8 + lr8) * ALD2 + hb + k2*16 + lc8*8) * 2;
            ldm_x2(kh, aKh + offB);
            ldm_x2(kl, aKl + offB);
            mma16816(sacc[nt], qh, kh);
            mma16816(sacc[nt], qh, kl);
            mma16816(sacc[nt], ql, kh);
        }
    }

    const float SC = 0.17677669529663687f;
    float s0 = 0.f, s1 = 0.f;
    #pragma unroll
    for (int nt = 0; nt < 8; nt++) {
        sacc[nt][0] = __expf(sacc[nt][0] * SC);
        sacc[nt][1] = __expf(sacc[nt][1] * SC);
        sacc[nt][2] = __expf(sacc[nt][2] * SC);
        sacc[nt][3] = __expf(sacc[nt][3] * SC);
        s0 += sacc[nt][0] + sacc[nt][1];
        s1 += sacc[nt][2] + sacc[nt][3];
    }
    s0 += __shfl_xor_sync(0xffffffffu, s0, 1);
    s0 += __shfl_xor_sync(0xffffffffu, s0, 2);
    s1 += __shfl_xor_sync(0xffffffffu, s1, 1);
    s1 += __shfl_xor_sync(0xffffffffu, s1, 2);
    const float inv0 = 1.0f / s0;
    const float inv1 = 1.0f / s1;

    float oacc[4][4];
    #pragma unroll
    for (int nt = 0; nt < 4; nt++)
        #pragma unroll
        for (int j = 0; j < 4; j++) oacc[nt][j] = 0.f;

    #pragma unroll
    for (int kk = 0; kk < 4; kk++) {
        uint32_t ph[4], pl[4];
        #pragma unroll
        for (int h2 = 0; h2 < 2; h2++) {
            float* sp = sacc[kk*2 + h2];
            #pragma unroll
            for (int g = 0; g < 2; g++) {
                float p0 = sp[g*2], p1 = sp[g*2 + 1];
                __nv_bfloat16 hh0 = __float2bfloat16(p0);
                __nv_bfloat16 hh1 = __float2bfloat16(p1);
                ph[h2*2 + g] = bpack(hh0, hh1);
                pl[h2*2 + g] = bpack(
                    __float2bfloat16(p0 - __bfloat162float(hh0)),
                    __float2bfloat16(p1 - __bfloat162float(hh1)));
            }
        }
        #pragma unroll
        for (int nt = 0; nt < 4; nt++) {
            uint32_t vh[2], vl[2];
            uint32_t offV = ((uint32_t)(kk*16 + lr16) * ALD2 + hb + nt*8) * 2;
            ldm_x2_trans(vh, aVh + offV);
            ldm_x2_trans(vl, aVl + offV);
            mma16816(oacc[nt], ph, vh);
            mma16816(oacc[nt], ph, vl);
            mma16816(oacc[nt], pl, vh);
        }
    }

    const int cit = (lane & 3) * 2;
    const int oc  = co + hb;
    int r0 = w4*16 + (lane >> 2);
    int r1 = r0 + 8;
    int i0 = r0 >> 3, j0 = r0 & 7;
    int i1 = r1 >> 3, j1 = r1 & 7;
    size_t t0 = qbase + (size_t)(wh * WS + i0) * qW + (ww * WS + j0);
    size_t t1 = qbase + (size_t)(wh * WS + i1) * qW + (ww * WS + j1);
    size_t ob0 = t0 * C_DIM + oc + cit;
    size_t ob1 = t1 * C_DIM + oc + cit;

    #pragma unroll
    for (int nt = 0; nt < 4; nt++) {
        *(__half2*)(O + ob0 + nt*8) =
            __floats2half2_rn(oacc[nt][0] * inv0, oacc[nt][1] * inv0);
        *(__half2*)(O + ob1 + nt*8) =
            __floats2half2_rn(oacc[nt][2] * inv1, oacc[nt][3] * inv1);
    }
}

// ==================================================================
// 4x4 average pool (NHWC), fp32 + fp16 out
// ==================================================================
__global__ __launch_bounds__(256)
void avgpool_kernel(const float* __restrict__ in, float* __restrict__ outf,
                    __half* __restrict__ outh)
{
    int t = blockIdx.x;
    int c = threadIdx.x;
    int n = t / (H1 * W1);
    int r = t % (H1 * W1);
    int oh = r / W1, ow = r % W1;
    float s = 0.f;
    #pragma unroll
    for (int dy = 0; dy < 4; dy++)
        #pragma unroll
        for (int dx = 0; dx < 4; dx++) {
            size_t tok = (size_t)n * H0 * W0 + (size_t)(oh * 4 + dy) * W0 + (ow * 4 + dx);
            s += in[tok * C_DIM + c];
        }
    s *= (1.0f / 16.0f);
    size_t o = (size_t)t * C_DIM + c;
    outf[o] = s;
    outh[o] = __float2half(s);
}

// ==================================================================
// Host side
// ==================================================================
#define WQKV  0
#define WSAF  196608
#define WCAQ  262144
#define WCAKV 327680
#define WCAF  458752
#define WW1   524288
#define WW2   786432

extern "C" void kernel_launch(void* const* d_in, const int* in_sizes, int n_in,
                              void* d_out, int out_size)
{
    const float* x       = (const float*)d_in[0];
    const float* sa_wq   = (const float*)d_in[1];
    const float* sa_wk   = (const float*)d_in[2];
    const float* sa_wv   = (const float*)d_in[3];
    const float* sa_wf   = (const float*)d_in[4];
    const float* sa_bf   = (const float*)d_in[5];
    const float* ca_wq   = (const float*)d_in[6];
    const float* ca_wk   = (const float*)d_in[7];
    const float* ca_wv   = (const float*)d_in[8];
    const float* ca_wf   = (const float*)d_in[9];
    const float* ca_bf   = (const float*)d_in[10];
    const float* ln_self_g = (const float*)d_in[11];
    const float* ln_self_b = (const float*)d_in[12];
    const float* ln_cross_g= (const float*)d_in[13];
    const float* ln_cross_b= (const float*)d_in[14];
    const float* ffn_w1  = (const float*)d_in[15];
    const float* ffn_b1  = (const float*)d_in[16];
    const float* ffn_w2  = (const float*)d_in[17];
    const float* ffn_b2  = (const float*)d_in[18];
    const float* ln_out_g= (const float*)d_in[19];
    const float* ln_out_b= (const float*)d_in[20];
    float* out = (float*)d_out;

    float *bufA, *bufB, *bufL0;
    __nv_bfloat16 *qkvh, *qkvl, *ash, *asl, *fh, *fl;
    __half *wph, *wpl;
    cudaGetSymbolAddress((void**)&bufA,  g_bufA);
    cudaGetSymbolAddress((void**)&bufB,  g_bufB);
    cudaGetSymbolAddress((void**)&bufL0, g_bufL0);
    cudaGetSymbolAddress((void**)&qkvh,  g_qkvh);
    cudaGetSymbolAddress((void**)&qkvl,  g_qkvl);
    cudaGetSymbolAddress((void**)&ash,   g_ash);
    cudaGetSymbolAddress((void**)&asl,   g_asl);
    cudaGetSymbolAddress((void**)&fh,    g_fh);
    cudaGetSymbolAddress((void**)&fl,    g_fl);
    cudaGetSymbolAddress((void**)&wph,   g_wph);
    cudaGetSymbolAddress((void**)&wpl,   g_wpl);

    __half* actA = (__half*)ash;    /* generic fp16 activation buffer */
    __half* actB = (__half*)asl;    /* second fp16 activation buffer */
    __half* f16  = (__half*)fh;     /* fp16 FFN intermediate (fh dead by then) */

    cudaFuncSetAttribute(gemm_fp16_kernel,
                         cudaFuncAttributeMaxDynamicSharedMemorySize, GEMMH_SMEM);
    cudaFuncSetAttribute(win_attn_kernel,
                         cudaFuncAttributeMaxDynamicSharedMemorySize, ATTN_SMEM);

    dim3 tb(32, 8);

    auto gemm = [&](int M, int N, int K, const __half* A,
                    const __half* Bh, const __half* Bl,
                    const float* bias, const float* resid,
                    const float* lnG, const float* lnB,
                    float* Cf, __nv_bfloat16* Ch, __nv_bfloat16* Cl,
                    __half* Cp, int relu) {
        dim3 grid(N / BN, M / BM);
        gemm_fp16_kernel<<<grid, 256, GEMMH_SMEM>>>(M, N, K, A, Bh, Bl,
                                                    bias, resid, lnG, lnB,
                                                    Cf, Ch, Cl, Cp, relu);
    };

    // --- batched fp16 weight prep (one launch) ---
    {
        WPrepArgs a;
        const float* srcs[10] = {sa_wq, sa_wk, sa_wv, sa_wf, ca_wq,
                                 ca_wk, ca_wv, ca_wf, ffn_w1, ffn_w2};
        int Ks[10]  = {256,256,256,256,256,256,256,256,256,1024};
        int Ns[10]  = {256,256,256,256,256,256,256,256,1024,256};
        int offs[10] = {WQKV, WQKV + 65536, WQKV + 131072, WSAF,
                        WCAQ, WCAKV, WCAKV + 65536, WCAF, WW1, WW2};
        for (int j = 0; j < 10; j++) {
            a.src[j] = srcs[j]; a.K[j] = Ks[j]; a.N[j] = Ns[j]; a.off[j] = offs[j];
        }
        wprep_h_kernel<<<dim3(32, 32, 10), tb>>>(a, wph, wpl);
    }

    // 0. NCHW -> NHWC (+fp16)
    transpose_split_kernel<<<dim3(H0*W0/32, C_DIM/32, NB), tb>>>(x, bufA, actA,
                                                                 C_DIM, H0*W0);

    // 1. Self-attention level 0
    gemm(T0, 768, 256, actA, wph + WQKV, wpl + WQKV,
         nullptr, nullptr, nullptr, nullptr, nullptr, qkvh, qkvl, nullptr, 0);
    win_attn_kernel<<<dim3(NB*16*16, NHEADS/HG), 256, ATTN_SMEM>>>(
        qkvh, qkvl, 768, qkvh + 256, qkvl + 256, qkvh + 512, qkvl + 512, 768,
        actA, H0, W0, H0, W0, WS);
    // SAF L0: fp32 L0 (resid for CAF) + fused self-LN + fp16 for CAQ
    gemm(T0, 256, 256, actA, wph + WSAF, wpl + WSAF,
         sa_bf, bufA, ln_self_g, ln_self_b, bufL0, nullptr, nullptr, actB, 0);

    // 2. avgpool
    avgpool_kernel<<<T1, 256>>>(bufL0, bufB, actA);

    // 3. Self-attention level 1
    gemm(T1, 768, 256, actA, wph + WQKV, wpl + WQKV,
         nullptr, nullptr, nullptr, nullptr, nullptr, qkvh, qkvl, nullptr, 0);
    win_attn_kernel<<<dim3(NB*4*4, NHEADS/HG), 256, ATTN_SMEM>>>(
        qkvh, qkvl, 768, qkvh + 256, qkvl + 256, qkvh + 512, qkvl + 512, 768,
        actA, H1, W1, H1, W1, WS);
    // SAF L1 (in-place fp16 out: CTA-row-ownership makes this safe)
    gemm(T1, 256, 256, actA, wph + WSAF, wpl + WSAF,
         sa_bf, bufB, ln_self_g, ln_self_b, nullptr, nullptr, nullptr, actA, 0);

    // 4. Cross-attention
    gemm(T1, 512, 256, actA, wph + WCAKV, wpl + WCAKV,
         nullptr, nullptr, nullptr, nullptr, nullptr, qkvh, qkvl, nullptr, 0);
    gemm(T0, 256, 256, actB, wph + WCAQ, wpl + WCAQ,
         nullptr, nullptr, nullptr, nullptr, nullptr, fh, fl, nullptr, 0);
    win_attn_kernel<<<dim3(NB*16*16, NHEADS/HG), 256, ATTN_SMEM>>>(
        fh, fl, 256, qkvh, qkvl, qkvh + 256, qkvl + 256, 512,
        actA, H0, W0, H1, W1, 2);
    // CAF: fp32 out (FFN2 residual) + fused cross-LN + fp16 for FFN1
    gemm(T0, 256, 256, actA, wph + WCAF, wpl + WCAF,
         ca_bf, bufL0, ln_cross_g, ln_cross_b, bufB, nullptr, nullptr, actB, 0);

    // 5. FFN (+fused final LN on FFN2)
    gemm(T0, 1024, 256, actB, wph + WW1, wpl + WW1,
         ffn_b1, nullptr, nullptr, nullptr, nullptr, nullptr, nullptr, f16, 1);
    gemm(T0, 256, 1024, f16, wph + WW2, wpl + WW2,
         ffn_b2, bufB, ln_out_g, ln_out_b, bufL0, nullptr, nullptr, nullptr, 0);

    // 6. NHWC -> NCHW
    transpose_split_kernel<<<dim3(C_DIM/32, H0*W0/32, NB), tb>>>(bufL0, out,
        nullptr, H0*W0, C_DIM);
}